// round 10
// baseline (speedup 1.0000x reference)
#include <cuda_runtime.h>
#include <cuda_fp16.h>
#include <cstdint>

#define L_TOK 3120
#define DIM 1536
#define NH 12
#define HD 128
#define FR 1560
#define SCALE_F 0.08838834764831845f

// ---------------- scratch ----------------
__device__ __align__(16) __half g_q[L_TOK * DIM];       // Q fp16 (post rms_rope)
__device__ __align__(16) __half g_k[L_TOK * DIM];
__device__ __align__(16) __half g_v[L_TOK * DIM];       // V fp16, plain [L][DIM]
__device__ __align__(16) __half g_a[L_TOK * DIM];       // attn out fp16
__device__ __align__(16) __half g_xh[L_TOK * DIM];      // x fp16
__device__ __align__(16) __half g_wqkv[3 * DIM * DIM];  // [4608][1536] fp16 (W^T)
__device__ __align__(16) __half g_wo[DIM * DIM];        // wo^T fp16

// ---------------- helpers ----------------
__device__ __forceinline__ void mma_f16(float c[4], const unsigned a[4],
                                        const unsigned* b) {
  asm volatile(
      "mma.sync.aligned.m16n8k16.row.col.f32.f16.f16.f32 "
      "{%0,%1,%2,%3},{%4,%5,%6,%7},{%8,%9},{%0,%1,%2,%3};"
      : "+f"(c[0]), "+f"(c[1]), "+f"(c[2]), "+f"(c[3])
      : "r"(a[0]), "r"(a[1]), "r"(a[2]), "r"(a[3]), "r"(b[0]), "r"(b[1]));
}
__device__ __forceinline__ void ldsm4(unsigned r[4], uint32_t addr) {
  asm volatile(
      "ldmatrix.sync.aligned.m8n8.x4.shared.b16 {%0,%1,%2,%3}, [%4];"
      : "=r"(r[0]), "=r"(r[1]), "=r"(r[2]), "=r"(r[3]) : "r"(addr));
}
__device__ __forceinline__ void ldsm4t(unsigned r[4], uint32_t addr) {
  asm volatile(
      "ldmatrix.sync.aligned.m8n8.x4.trans.shared.b16 {%0,%1,%2,%3}, [%4];"
      : "=r"(r[0]), "=r"(r[1]), "=r"(r[2]), "=r"(r[3]) : "r"(addr));
}
__device__ __forceinline__ uint32_t smem_u32(const void* p) {
  uint32_t a;
  asm("{ .reg .u64 t; cvta.to.shared.u64 t, %1; cvt.u32.u64 %0, t; }"
      : "=r"(a) : "l"(p));
  return a;
}
__device__ __forceinline__ unsigned h2u(float a, float b) {
  __half2 h = __floats2half2_rn(a, b);
  return *(unsigned*)&h;
}

// ---------------- cvt kernels ----------------
__global__ __launch_bounds__(256) void cvt_x_kernel(const float* __restrict__ s,
                                                    __half* __restrict__ d, int n4) {
  int i = blockIdx.x * 256 + threadIdx.x;
  if (i < n4) {
    float4 v = *(const float4*)(s + 4 * (size_t)i);
    __half2* dp = (__half2*)(d + 4 * (size_t)i);
    dp[0] = __floats2half2_rn(v.x, v.y);
    dp[1] = __floats2half2_rn(v.z, v.w);
  }
}

__global__ __launch_bounds__(256) void cvt_w_kernel(
    const float* __restrict__ w0, const float* __restrict__ w1,
    const float* __restrict__ w2, const float* __restrict__ w3,
    __half* __restrict__ qkv, __half* __restrict__ wot) {
  __shared__ float tile[32][33];
  const int z = blockIdx.z;
  const float* src = (z == 0) ? w0 : (z == 1) ? w1 : (z == 2) ? w2 : w3;
  __half* dst = (z == 3) ? wot : (qkv + (size_t)z * DIM * DIM);
  const int k0 = blockIdx.x * 32, n0 = blockIdx.y * 32;
  const int x = threadIdx.x, y = threadIdx.y;
#pragma unroll
  for (int i = 0; i < 4; i++)
    tile[y + 8 * i][x] = src[(size_t)(k0 + y + 8 * i) * DIM + n0 + x];
  __syncthreads();
#pragma unroll
  for (int i = 0; i < 4; i++)
    dst[(size_t)(n0 + y + 8 * i) * DIM + k0 + x] = __float2half(tile[x][y + 8 * i]);
}

// ---------------- fp16 GEMM: C[M][N] = A[M][K] @ Wt[N][K]^T ----------------
// CTA 64x256, BK=32, 256 thr (8 warps: 2m x 4n). 4-stage cp.async,
// one __syncthreads per mainloop iter, prefetch distance 3.
#define AST 40
#define A_HS (64 * AST)
#define B_HS (256 * AST)
#define NST 4
#define GEMM_SMEM (NST * (A_HS + B_HS) * 2)

template <int QKV>
__global__ __launch_bounds__(256, 2) void gemm_f16(
    const __half* __restrict__ A, const __half* __restrict__ Wt,
    const float* __restrict__ b0, const float* __restrict__ b1,
    const float* __restrict__ b2, float* __restrict__ Cf,
    __half* __restrict__ H0, __half* __restrict__ H1,
    __half* __restrict__ H2, int M) {
  extern __shared__ __half smh[];
  const uint32_t sm_u = smem_u32(smh);

  const int t = threadIdx.x;
  const int m0 = blockIdx.y * 64;
  const int n0g = blockIdx.x * 256;
  const int warp = t >> 5, lane = t & 31;
  const int wm = (warp & 1) * 32;
  const int wn = (warp >> 1) * 64;
  const int g = lane >> 2, t4 = lane & 3;
  const int ar = lane & 15, aklo = (lane & 16) >> 1;
  const int br = (lane & 7) + ((lane & 16) >> 1), bklo = lane & 8;

  float c[2][8][4];
#pragma unroll
  for (int i = 0; i < 2; i++)
#pragma unroll
    for (int j = 0; j < 8; j++)
#pragma unroll
      for (int r = 0; r < 4; r++) c[i][j][r] = 0.f;

  auto prefetch = [&](int buf, int k0) {
    __half* asb = smh + buf * (A_HS + B_HS);
    __half* bsb = asb + A_HS;
    {
      int row = t >> 2, c8 = (t & 3) << 3;
      int gr = m0 + row;
      if (gr >= M) gr = M - 1;
      unsigned dst = (unsigned)__cvta_generic_to_shared(asb + row * AST + c8);
      asm volatile("cp.async.cg.shared.global [%0], [%1], 16;" ::"r"(dst),
                   "l"(A + (size_t)gr * DIM + k0 + c8));
    }
#pragma unroll
    for (int i = 0; i < 4; i++) {
      int idx = t + 256 * i;
      int row = idx >> 2, c8 = (idx & 3) << 3;
      unsigned dst = (unsigned)__cvta_generic_to_shared(bsb + row * AST + c8);
      asm volatile("cp.async.cg.shared.global [%0], [%1], 16;" ::"r"(dst),
                   "l"(Wt + (size_t)(n0g + row) * DIM + k0 + c8));
    }
  };

  prefetch(0, 0);
  asm volatile("cp.async.commit_group;");
  prefetch(1, 32);
  asm volatile("cp.async.commit_group;");
  prefetch(2, 64);
  asm volatile("cp.async.commit_group;");

  const int KT = DIM / 32;
  for (int kt = 0; kt < KT; kt++) {
    const int s = kt & 3;
    asm volatile("cp.async.wait_group 2;");   // stage kt resident
    __syncthreads();                          // all warps past mma(kt-1), data visible

    const uint32_t au = sm_u + s * (A_HS + B_HS) * 2;
    const uint32_t bu = au + A_HS * 2;

#pragma unroll
    for (int kk = 0; kk < 32; kk += 16) {
      unsigned av[2][4], bv[4][4];
#pragma unroll
      for (int am = 0; am < 2; am++)
        ldsm4(av[am], au + ((wm + 16 * am + ar) * AST + kk + aklo) * 2);
#pragma unroll
      for (int bn = 0; bn < 4; bn++)
        ldsm4(bv[bn], bu + ((wn + 16 * bn + br) * AST + kk + bklo) * 2);
#pragma unroll
      for (int am = 0; am < 2; am++)
#pragma unroll
        for (int an = 0; an < 8; an++)
          mma_f16(c[am][an], av[am], (an & 1) ? (bv[an >> 1] + 2) : bv[an >> 1]);
    }

    if (kt + 3 < KT) prefetch((kt + 3) & 3, (kt + 3) * 32);
    asm volatile("cp.async.commit_group;");   // one commit per iter (may be empty)
  }

  // ---- epilogue ----
  int part = 0, ncol0 = n0g;
  const float* bias = b0;
  if (QKV) {
    part = n0g / DIM;
    ncol0 = n0g - part * DIM;
    bias = (part == 0) ? b0 : (part == 1) ? b1 : b2;
  }
  __half* H = QKV ? ((part == 0) ? H0 : (part == 1) ? H1 : H2) : (__half*)0;
#pragma unroll
  for (int am = 0; am < 2; am++) {
    const int r0 = m0 + wm + 16 * am + g;
    const int r1 = r0 + 8;
#pragma unroll
    for (int an = 0; an < 8; an++) {
      const int col = ncol0 + wn + 8 * an + 2 * t4;
      const float bb0 = bias[col], bb1 = bias[col + 1];
      if (!QKV) {
        if (r0 < M)
          *(float2*)(Cf + (size_t)r0 * DIM + col) =
              make_float2(c[am][an][0] + bb0, c[am][an][1] + bb1);
        if (r1 < M)
          *(float2*)(Cf + (size_t)r1 * DIM + col) =
              make_float2(c[am][an][2] + bb0, c[am][an][3] + bb1);
      } else {
        if (r0 < M)
          *(__half2*)(H + (size_t)r0 * DIM + col) =
              __floats2half2_rn(c[am][an][0] + bb0, c[am][an][1] + bb1);
        if (r1 < M)
          *(__half2*)(H + (size_t)r1 * DIM + col) =
              __floats2half2_rn(c[am][an][2] + bb0, c[am][an][3] + bb1);
      }
    }
  }
}

// ---------------- fused RMSNorm + RoPE (fp16 in/out), 512 thr ----------------
__global__ __launch_bounds__(512) void rms_rope_kernel(
    __half* __restrict__ qbuf, __half* __restrict__ kbuf,
    const float* __restrict__ gq, const float* __restrict__ gk,
    const float* __restrict__ cosp, const float* __restrict__ sinp) {
  const int l = blockIdx.x;
  const int half = threadIdx.x >> 8;          // 0 -> q, 1 -> k
  __half* row = (half == 0) ? (qbuf + (size_t)l * DIM) : (kbuf + (size_t)l * DIM);
  const float* g = (half == 0) ? gq : gk;
  const int t = threadIdx.x & 255;

  float2 v[3], cs[3], gv[3];
  float ss = 0.f;
#pragma unroll
  for (int j = 0; j < 3; j++) {
    int p = t + 256 * j;
    v[j] = __half22float2(((const __half2*)row)[p]);
    int hd2 = p & 63;
    cs[j] = make_float2(cosp[l * 64 + hd2], sinp[l * 64 + hd2]);
    gv[j] = *(const float2*)(g + 2 * p);
    ss += v[j].x * v[j].x + v[j].y * v[j].y;
  }
#pragma unroll
  for (int off = 16; off > 0; off >>= 1)
    ss += __shfl_xor_sync(0xffffffffu, ss, off);
  __shared__ float red[2][8];
  if ((t & 31) == 0) red[half][t >> 5] = ss;
  __syncthreads();
  float tot = 0.f;
#pragma unroll
  for (int w = 0; w < 8; w++) tot += red[half][w];
  const float r = rsqrtf(tot * (1.0f / (float)DIM) + 1e-6f);

#pragma unroll
  for (int j = 0; j < 3; j++) {
    int p = t + 256 * j;
    float e = v[j].x * r * gv[j].x;
    float o = v[j].y * r * gv[j].y;
    ((__half2*)row)[p] =
        __floats2half2_rn(e * cs[j].x - o * cs[j].y, e * cs[j].y + o * cs[j].x);
  }
}

// ---------------- fp16 flash attention, warp-local softmax, occ 3 ----------
#define TILE_H (64 * 136)
#define ATT_SMEM (4 * TILE_H * 2)   // Q + K0 + K1 + V  (68 KB)

__global__ __launch_bounds__(128, 3) void attn_f16_kernel(
    const __half* __restrict__ q, const __half* __restrict__ k,
    const __half* __restrict__ v, __half* __restrict__ o) {
  extern __shared__ __half smh[];
  __half* Qs = smh;
  const uint32_t qs_u = smem_u32(Qs);
  const uint32_t k0_u = qs_u + TILE_H * 2;
  const uint32_t k1_u = k0_u + TILE_H * 2;
  const uint32_t vb_u = k1_u + TILE_H * 2;

  const int t = threadIdx.x, lane = t & 31, w = t >> 5;
  const int g = lane >> 2, t4 = lane & 3;
  const int q0 = (int)(gridDim.x - 1 - blockIdx.x) * 64;   // LPT: long blocks first
  const int h = blockIdx.y;
  const int rw = w * 16;
  const int ar = lane & 15, aklo = (lane & 16) >> 1;
  const int br = (lane & 7) + ((lane & 16) >> 1), bklo = lane & 8;
  const int vrow = lane & 15, vcol = (lane >> 4) << 3;

  auto load_tile = [&](const __half* src, uint32_t dst_u, int kb) {
#pragma unroll
    for (int i = 0; i < 8; i++) {
      int idx = t + 128 * i, r = idx >> 4, c8 = (idx & 15) << 3;
      int kr = kb + r;
      int sz = (kr < L_TOK) ? 16 : 0;
      if (kr >= L_TOK) kr = L_TOK - 1;
      asm volatile("cp.async.cg.shared.global [%0], [%1], 16, %2;" ::
                   "r"(dst_u + (uint32_t)(r * 136 + c8) * 2),
                   "l"(src + (size_t)kr * DIM + h * HD + c8), "r"(sz));
    }
  };

  load_tile(q, qs_u, q0);
  load_tile(k, k0_u, 0);
  asm volatile("cp.async.commit_group;");

  float oa[16][4];
#pragma unroll
  for (int a = 0; a < 16; a++)
#pragma unroll
    for (int r = 0; r < 4; r++) oa[a][r] = 0.f;

  float m0 = -3.0e38f, m1 = -3.0e38f, l0 = 0.f, l1 = 0.f;
  const int km0 = (q0 + rw + g < FR) ? FR : L_TOK;
  const int km1 = (q0 + rw + 8 + g < FR) ? FR : L_TOK;

  int qlast = q0 + 63; if (qlast >= L_TOK) qlast = L_TOK - 1;
  const int nt = (((qlast < FR) ? FR : L_TOK) + 63) >> 6;

  // Q fragments are loop-invariant: load once after Q arrives (kt==0 path).
  unsigned qa[8][4];

  for (int kt = 0; kt < nt; kt++) {
    const int kb = kt * 64;
    const uint32_t ku = (kt & 1) ? k1_u : k0_u;
    asm volatile("cp.async.wait_group 0;");
    __syncthreads();

    load_tile(v, vb_u, kb);
    asm volatile("cp.async.commit_group;");
    const bool pk = (kt + 1 < nt);
    if (pk) {
      load_tile(k, ((kt + 1) & 1) ? k1_u : k0_u, kb + 64);
      asm volatile("cp.async.commit_group;");
    }

    if (kt == 0) {
#pragma unroll
      for (int k16 = 0; k16 < 8; k16++)
        ldsm4(qa[k16], qs_u + ((rw + ar) * 136 + k16 * 16 + aklo) * 2);
    }

    // ---- S = Q K^T ----
    float s_[8][4];
#pragma unroll
    for (int a = 0; a < 8; a++)
#pragma unroll
      for (int r = 0; r < 4; r++) s_[a][r] = 0.f;

#pragma unroll
    for (int k16 = 0; k16 < 8; k16++) {
      const int kk = k16 * 16;
      unsigned bv[4][4];
#pragma unroll
      for (int bn = 0; bn < 4; bn++)
        ldsm4(bv[bn], ku + ((16 * bn + br) * 136 + kk + bklo) * 2);
#pragma unroll
      for (int a = 0; a < 8; a++)
        mma_f16(s_[a], qa[k16], (a & 1) ? (bv[a >> 1] + 2) : bv[a >> 1]);
    }

    // ---- scale + mask ----
#pragma unroll
    for (int a = 0; a < 8; a++) {
      int cb = kb + 8 * a + 2 * t4;
      s_[a][0] = (cb     < km0) ? s_[a][0] * SCALE_F : -3.0e38f;
      s_[a][1] = (cb + 1 < km0) ? s_[a][1] * SCALE_F : -3.0e38f;
      s_[a][2] = (cb     < km1) ? s_[a][2] * SCALE_F : -3.0e38f;
      s_[a][3] = (cb + 1 < km1) ? s_[a][3] * SCALE_F : -3.0e38f;
    }

    // ---- warp-local softmax ----
    float mx0 = -3.0e38f, mx1 = -3.0e38f;
#pragma unroll
    for (int a = 0; a < 8; a++) {
      mx0 = fmaxf(mx0, fmaxf(s_[a][0], s_[a][1]));
      mx1 = fmaxf(mx1, fmaxf(s_[a][2], s_[a][3]));
    }
    mx0 = fmaxf(mx0, __shfl_xor_sync(0xffffffffu, mx0, 1));
    mx0 = fmaxf(mx0, __shfl_xor_sync(0xffffffffu, mx0, 2));
    mx1 = fmaxf(mx1, __shfl_xor_sync(0xffffffffu, mx1, 1));
    mx1 = fmaxf(mx1, __shfl_xor_sync(0xffffffffu, mx1, 2));
    const float mn0 = fmaxf(m0, mx0), mn1 = fmaxf(m1, mx1);
    const float cr0 = __expf(m0 - mn0), cr1 = __expf(m1 - mn1);
    m0 = mn0; m1 = mn1;

    unsigned pa[4][4];
    float sl0 = 0.f, sl1 = 0.f;
#pragma unroll
    for (int jk = 0; jk < 4; jk++) {
#pragma unroll
      for (int hh = 0; hh < 2; hh++) {
        const int a = 2 * jk + hh;
        float e0 = __expf(s_[a][0] - mn0);
        float e1 = __expf(s_[a][1] - mn0);
        float e2 = __expf(s_[a][2] - mn1);
        float e3 = __expf(s_[a][3] - mn1);
        sl0 += e0 + e1; sl1 += e2 + e3;
        pa[jk][2 * hh] = h2u(e0, e1);
        pa[jk][2 * hh + 1] = h2u(e2, e3);
      }
    }
    sl0 += __shfl_xor_sync(0xffffffffu, sl0, 1);
    sl0 += __shfl_xor_sync(0xffffffffu, sl0, 2);
    sl1 += __shfl_xor_sync(0xffffffffu, sl1, 1);
    sl1 += __shfl_xor_sync(0xffffffffu, sl1, 2);
    l0 = l0 * cr0 + sl0;
    l1 = l1 * cr1 + sl1;

#pragma unroll
    for (int a = 0; a < 16; a++) {
      oa[a][0] *= cr0; oa[a][1] *= cr0;
      oa[a][2] *= cr1; oa[a][3] *= cr1;
    }

    if (pk) asm volatile("cp.async.wait_group 1;");
    else    asm volatile("cp.async.wait_group 0;");
    __syncthreads();

    // ---- O += P V ----
#pragma unroll
    for (int jk = 0; jk < 4; jk++) {
      const int kk = jk * 16;
      unsigned bv[8][4];
#pragma unroll
      for (int nb = 0; nb < 8; nb++)
        ldsm4t(bv[nb], vb_u + ((kk + vrow) * 136 + 16 * nb + vcol) * 2);
#pragma unroll
      for (int na = 0; na < 16; na++)
        mma_f16(oa[na], pa[jk], (na & 1) ? (bv[na >> 1] + 2) : bv[na >> 1]);
    }
  }

  // ---- epilogue ----
  const float inv0 = 1.0f / l0, inv1 = 1.0f / l1;
  const int gr0 = q0 + rw + g, gr1 = gr0 + 8;
#pragma unroll
  for (int na = 0; na < 16; na++) {
    const int col = h * HD + 8 * na + 2 * t4;
    if (gr0 < L_TOK)
      *(__half2*)(o + (size_t)gr0 * DIM + col) =
          __floats2half2_rn(oa[na][0] * inv0, oa[na][1] * inv0);
    if (gr1 < L_TOK)
      *(__half2*)(o + (size_t)gr1 * DIM + col) =
          __floats2half2_rn(oa[na][2] * inv1, oa[na][3] * inv1);
  }
}

// ---------------- launch ----------------
extern "C" void kernel_launch(void* const* d_in, const int* in_sizes, int n_in,
                              void* d_out, int out_size) {
  const float* x  = (const float*)d_in[0];
  const float* wq = (const float*)d_in[1];
  const float* wk = (const float*)d_in[2];
  const float* wv = (const float*)d_in[3];
  const float* wo = (const float*)d_in[4];
  const float* bq = (const float*)d_in[5];
  const float* bk = (const float*)d_in[6];
  const float* bv = (const float*)d_in[7];
  const float* bo = (const float*)d_in[8];
  const float* gq = (const float*)d_in[9];
  const float* gk = (const float*)d_in[10];
  const float* fc = (const float*)d_in[11];
  const float* fs = (const float*)d_in[12];
  float* out = (float*)d_out;

  __half *qb, *kb, *vb, *ab, *xh, *wqkv, *wot;
  cudaGetSymbolAddress((void**)&qb, g_q);
  cudaGetSymbolAddress((void**)&kb, g_k);
  cudaGetSymbolAddress((void**)&vb, g_v);
  cudaGetSymbolAddress((void**)&ab, g_a);
  cudaGetSymbolAddress((void**)&xh, g_xh);
  cudaGetSymbolAddress((void**)&wqkv, g_wqkv);
  cudaGetSymbolAddress((void**)&wot, g_wo);

  cudaFuncSetAttribute(gemm_f16<1>, cudaFuncAttributeMaxDynamicSharedMemorySize, GEMM_SMEM);
  cudaFuncSetAttribute(gemm_f16<0>, cudaFuncAttributeMaxDynamicSharedMemorySize, GEMM_SMEM);
  cudaFuncSetAttribute(attn_f16_kernel, cudaFuncAttributeMaxDynamicSharedMemorySize, ATT_SMEM);

  int nx4 = L_TOK * DIM / 4;
  cvt_x_kernel<<<(nx4 + 255) / 256, 256>>>(x, xh, nx4);
  cvt_w_kernel<<<dim3(DIM / 32, DIM / 32, 4), dim3(32, 8)>>>(wq, wk, wv, wo, wqkv, wot);

  gemm_f16<1><<<dim3(3 * DIM / 256, (L_TOK + 63) / 64), 256, GEMM_SMEM>>>(
      xh, wqkv, bq, bk, bv, nullptr, qb, kb, vb, L_TOK);

  rms_rope_kernel<<<L_TOK, 512>>>(qb, kb, gq, gk, fc, fs);

  attn_f16_kernel<<<dim3((L_TOK + 63) / 64, NH), 128, ATT_SMEM>>>(qb, kb, vb, ab);

  gemm_f16<0><<<dim3(DIM / 256, (L_TOK + 63) / 64), 256, GEMM_SMEM>>>(
      ab, wot, bo, nullptr, nullptr, out, nullptr, nullptr, nullptr, L_TOK);
}

// round 11
// speedup vs baseline: 1.0156x; 1.0156x over previous
#include <cuda_runtime.h>
#include <cuda_fp16.h>
#include <cstdint>

#define L_TOK 3120
#define DIM 1536
#define NH 12
#define HD 128
#define FR 1560
#define SCALE_F 0.08838834764831845f

// ---------------- scratch ----------------
__device__ __align__(16) __half g_q[L_TOK * DIM];       // Q fp16 (post rms_rope)
__device__ __align__(16) __half g_k[L_TOK * DIM];
__device__ __align__(16) __half g_v[L_TOK * DIM];       // V fp16, plain [L][DIM]
__device__ __align__(16) __half g_a[L_TOK * DIM];       // attn out fp16
__device__ __align__(16) __half g_xh[L_TOK * DIM];      // x fp16
__device__ __align__(16) __half g_wqkv[3 * DIM * DIM];  // [4608][1536] fp16 (W^T)
__device__ __align__(16) __half g_wo[DIM * DIM];        // wo^T fp16

// ---------------- helpers ----------------
__device__ __forceinline__ void mma_f16(float c[4], const unsigned a[4],
                                        const unsigned* b) {
  asm volatile(
      "mma.sync.aligned.m16n8k16.row.col.f32.f16.f16.f32 "
      "{%0,%1,%2,%3},{%4,%5,%6,%7},{%8,%9},{%0,%1,%2,%3};"
      : "+f"(c[0]), "+f"(c[1]), "+f"(c[2]), "+f"(c[3])
      : "r"(a[0]), "r"(a[1]), "r"(a[2]), "r"(a[3]), "r"(b[0]), "r"(b[1]));
}
__device__ __forceinline__ void ldsm4(unsigned r[4], uint32_t addr) {
  asm volatile(
      "ldmatrix.sync.aligned.m8n8.x4.shared.b16 {%0,%1,%2,%3}, [%4];"
      : "=r"(r[0]), "=r"(r[1]), "=r"(r[2]), "=r"(r[3]) : "r"(addr));
}
__device__ __forceinline__ void ldsm4t(unsigned r[4], uint32_t addr) {
  asm volatile(
      "ldmatrix.sync.aligned.m8n8.x4.trans.shared.b16 {%0,%1,%2,%3}, [%4];"
      : "=r"(r[0]), "=r"(r[1]), "=r"(r[2]), "=r"(r[3]) : "r"(addr));
}
__device__ __forceinline__ uint32_t smem_u32(const void* p) {
  uint32_t a;
  asm("{ .reg .u64 t; cvta.to.shared.u64 t, %1; cvt.u32.u64 %0, t; }"
      : "=r"(a) : "l"(p));
  return a;
}
__device__ __forceinline__ unsigned h2u(float a, float b) {
  __half2 h = __floats2half2_rn(a, b);
  return *(unsigned*)&h;
}

// ---------------- merged cvt kernel ----------------
// z = 0..3: weight transpose [K][N] -> [N][K] fp16 (z==3 -> wo)
// z = 4   : x fp32 -> fp16, grid-strided over the same 48x48 block shape
__global__ __launch_bounds__(256) void cvt_all_kernel(
    const float* __restrict__ x, const float* __restrict__ w0,
    const float* __restrict__ w1, const float* __restrict__ w2,
    const float* __restrict__ w3, __half* __restrict__ xh,
    __half* __restrict__ qkv, __half* __restrict__ wot) {
  const int z = blockIdx.z;
  if (z == 4) {
    const int nblk = gridDim.x * gridDim.y;
    const int bid = blockIdx.y * gridDim.x + blockIdx.x;
    const int n4 = L_TOK * DIM / 4;
    for (int i = bid * 256 + threadIdx.x; i < n4; i += nblk * 256) {
      float4 v = *(const float4*)(x + 4 * (size_t)i);
      __half2* dp = (__half2*)(xh + 4 * (size_t)i);
      dp[0] = __floats2half2_rn(v.x, v.y);
      dp[1] = __floats2half2_rn(v.z, v.w);
    }
    return;
  }
  __shared__ float tile[32][33];
  const float* src = (z == 0) ? w0 : (z == 1) ? w1 : (z == 2) ? w2 : w3;
  __half* dst = (z == 3) ? wot : (qkv + (size_t)z * DIM * DIM);
  const int k0 = blockIdx.x * 32, n0 = blockIdx.y * 32;
  const int xx = threadIdx.x & 31, yy = threadIdx.x >> 5;
#pragma unroll
  for (int i = 0; i < 4; i++)
    tile[yy + 8 * i][xx] = src[(size_t)(k0 + yy + 8 * i) * DIM + n0 + xx];
  __syncthreads();
#pragma unroll
  for (int i = 0; i < 4; i++)
    dst[(size_t)(n0 + yy + 8 * i) * DIM + k0 + xx] =
        __float2half(tile[xx][yy + 8 * i]);
}

// ---------------- fp16 GEMM: C[M][N] = A[M][K] @ Wt[N][K]^T ----------------
// CTA 64x256, BK=32, 256 thr (8 warps: 2m x 4n). 3-stage cp.async,
// one __syncthreads per mainloop iter (measured best config, round 9).
#define AST 40
#define A_HS (64 * AST)
#define B_HS (256 * AST)
#define NST 3
#define GEMM_SMEM (NST * (A_HS + B_HS) * 2)

template <int QKV>
__global__ __launch_bounds__(256, 2) void gemm_f16(
    const __half* __restrict__ A, const __half* __restrict__ Wt,
    const float* __restrict__ b0, const float* __restrict__ b1,
    const float* __restrict__ b2, float* __restrict__ Cf,
    __half* __restrict__ H0, __half* __restrict__ H1,
    __half* __restrict__ H2, int M) {
  extern __shared__ __half smh[];
  const uint32_t sm_u = smem_u32(smh);

  const int t = threadIdx.x;
  const int m0 = blockIdx.y * 64;
  const int n0g = blockIdx.x * 256;
  const int warp = t >> 5, lane = t & 31;
  const int wm = (warp & 1) * 32;
  const int wn = (warp >> 1) * 64;
  const int g = lane >> 2, t4 = lane & 3;
  const int ar = lane & 15, aklo = (lane & 16) >> 1;
  const int br = (lane & 7) + ((lane & 16) >> 1), bklo = lane & 8;

  float c[2][8][4];
#pragma unroll
  for (int i = 0; i < 2; i++)
#pragma unroll
    for (int j = 0; j < 8; j++)
#pragma unroll
      for (int r = 0; r < 4; r++) c[i][j][r] = 0.f;

  auto prefetch = [&](int buf, int k0) {
    __half* asb = smh + buf * (A_HS + B_HS);
    __half* bsb = asb + A_HS;
    {
      int row = t >> 2, c8 = (t & 3) << 3;
      int gr = m0 + row;
      if (gr >= M) gr = M - 1;
      unsigned dst = (unsigned)__cvta_generic_to_shared(asb + row * AST + c8);
      asm volatile("cp.async.cg.shared.global [%0], [%1], 16;" ::"r"(dst),
                   "l"(A + (size_t)gr * DIM + k0 + c8));
    }
#pragma unroll
    for (int i = 0; i < 4; i++) {
      int idx = t + 256 * i;
      int row = idx >> 2, c8 = (idx & 3) << 3;
      unsigned dst = (unsigned)__cvta_generic_to_shared(bsb + row * AST + c8);
      asm volatile("cp.async.cg.shared.global [%0], [%1], 16;" ::"r"(dst),
                   "l"(Wt + (size_t)(n0g + row) * DIM + k0 + c8));
    }
  };

  prefetch(0, 0);
  asm volatile("cp.async.commit_group;");
  prefetch(1, 32);
  asm volatile("cp.async.commit_group;");

  const int KT = DIM / 32;
  for (int kt = 0; kt < KT; kt++) {
    const int s = kt % 3;
    asm volatile("cp.async.wait_group 1;");   // stage kt resident
    __syncthreads();                          // all warps past mma(kt-1), data visible

    const uint32_t au = sm_u + s * (A_HS + B_HS) * 2;
    const uint32_t bu = au + A_HS * 2;

#pragma unroll
    for (int kk = 0; kk < 32; kk += 16) {
      unsigned av[2][4], bv[4][4];
#pragma unroll
      for (int am = 0; am < 2; am++)
        ldsm4(av[am], au + ((wm + 16 * am + ar) * AST + kk + aklo) * 2);
#pragma unroll
      for (int bn = 0; bn < 4; bn++)
        ldsm4(bv[bn], bu + ((wn + 16 * bn + br) * AST + kk + bklo) * 2);
#pragma unroll
      for (int am = 0; am < 2; am++)
#pragma unroll
        for (int an = 0; an < 8; an++)
          mma_f16(c[am][an], av[am], (an & 1) ? (bv[an >> 1] + 2) : bv[an >> 1]);
    }

    if (kt + 2 < KT) prefetch((kt + 2) % 3, (kt + 2) * 32);
    asm volatile("cp.async.commit_group;");   // one commit per iter (may be empty)
  }

  // ---- epilogue ----
  int part = 0, ncol0 = n0g;
  const float* bias = b0;
  if (QKV) {
    part = n0g / DIM;
    ncol0 = n0g - part * DIM;
    bias = (part == 0) ? b0 : (part == 1) ? b1 : b2;
  }
  __half* H = QKV ? ((part == 0) ? H0 : (part == 1) ? H1 : H2) : (__half*)0;
#pragma unroll
  for (int am = 0; am < 2; am++) {
    const int r0 = m0 + wm + 16 * am + g;
    const int r1 = r0 + 8;
#pragma unroll
    for (int an = 0; an < 8; an++) {
      const int col = ncol0 + wn + 8 * an + 2 * t4;
      const float bb0 = bias[col], bb1 = bias[col + 1];
      if (!QKV) {
        if (r0 < M)
          *(float2*)(Cf + (size_t)r0 * DIM + col) =
              make_float2(c[am][an][0] + bb0, c[am][an][1] + bb1);
        if (r1 < M)
          *(float2*)(Cf + (size_t)r1 * DIM + col) =
              make_float2(c[am][an][2] + bb0, c[am][an][3] + bb1);
      } else {
        if (r0 < M)
          *(__half2*)(H + (size_t)r0 * DIM + col) =
              __floats2half2_rn(c[am][an][0] + bb0, c[am][an][1] + bb1);
        if (r1 < M)
          *(__half2*)(H + (size_t)r1 * DIM + col) =
              __floats2half2_rn(c[am][an][2] + bb0, c[am][an][3] + bb1);
      }
    }
  }
}

// ---------------- fused RMSNorm + RoPE (fp16 in/out), 512 thr ----------------
__global__ __launch_bounds__(512) void rms_rope_kernel(
    __half* __restrict__ qbuf, __half* __restrict__ kbuf,
    const float* __restrict__ gq, const float* __restrict__ gk,
    const float* __restrict__ cosp, const float* __restrict__ sinp) {
  const int l = blockIdx.x;
  const int half = threadIdx.x >> 8;          // 0 -> q, 1 -> k
  __half* row = (half == 0) ? (qbuf + (size_t)l * DIM) : (kbuf + (size_t)l * DIM);
  const float* g = (half == 0) ? gq : gk;
  const int t = threadIdx.x & 255;

  float2 v[3], cs[3], gv[3];
  float ss = 0.f;
#pragma unroll
  for (int j = 0; j < 3; j++) {
    int p = t + 256 * j;
    v[j] = __half22float2(((const __half2*)row)[p]);
    int hd2 = p & 63;
    cs[j] = make_float2(cosp[l * 64 + hd2], sinp[l * 64 + hd2]);
    gv[j] = *(const float2*)(g + 2 * p);
    ss += v[j].x * v[j].x + v[j].y * v[j].y;
  }
#pragma unroll
  for (int off = 16; off > 0; off >>= 1)
    ss += __shfl_xor_sync(0xffffffffu, ss, off);
  __shared__ float red[2][8];
  if ((t & 31) == 0) red[half][t >> 5] = ss;
  __syncthreads();
  float tot = 0.f;
#pragma unroll
  for (int w = 0; w < 8; w++) tot += red[half][w];
  const float r = rsqrtf(tot * (1.0f / (float)DIM) + 1e-6f);

#pragma unroll
  for (int j = 0; j < 3; j++) {
    int p = t + 256 * j;
    float e = v[j].x * r * gv[j].x;
    float o = v[j].y * r * gv[j].y;
    ((__half2*)row)[p] =
        __floats2half2_rn(e * cs[j].x - o * cs[j].y, e * cs[j].y + o * cs[j].x);
  }
}

// ---------------- fp16 flash attention, warp-local softmax, occ 3 ----------
#define TILE_H (64 * 136)
#define ATT_SMEM (4 * TILE_H * 2)   // Q + K0 + K1 + V  (68 KB)

__global__ __launch_bounds__(128, 3) void attn_f16_kernel(
    const __half* __restrict__ q, const __half* __restrict__ k,
    const __half* __restrict__ v, __half* __restrict__ o) {
  extern __shared__ __half smh[];
  __half* Qs = smh;
  const uint32_t qs_u = smem_u32(Qs);
  const uint32_t k0_u = qs_u + TILE_H * 2;
  const uint32_t k1_u = k0_u + TILE_H * 2;
  const uint32_t vb_u = k1_u + TILE_H * 2;

  const int t = threadIdx.x, lane = t & 31, w = t >> 5;
  const int g = lane >> 2, t4 = lane & 3;
  const int q0 = (int)(gridDim.x - 1 - blockIdx.x) * 64;   // LPT: long blocks first
  const int h = blockIdx.y;
  const int rw = w * 16;
  const int ar = lane & 15, aklo = (lane & 16) >> 1;
  const int br = (lane & 7) + ((lane & 16) >> 1), bklo = lane & 8;
  const int vrow = lane & 15, vcol = (lane >> 4) << 3;

  auto load_tile = [&](const __half* src, uint32_t dst_u, int kb) {
#pragma unroll
    for (int i = 0; i < 8; i++) {
      int idx = t + 128 * i, r = idx >> 4, c8 = (idx & 15) << 3;
      int kr = kb + r;
      int sz = (kr < L_TOK) ? 16 : 0;
      if (kr >= L_TOK) kr = L_TOK - 1;
      asm volatile("cp.async.cg.shared.global [%0], [%1], 16, %2;" ::
                   "r"(dst_u + (uint32_t)(r * 136 + c8) * 2),
                   "l"(src + (size_t)kr * DIM + h * HD + c8), "r"(sz));
    }
  };

  load_tile(q, qs_u, q0);
  load_tile(k, k0_u, 0);
  asm volatile("cp.async.commit_group;");

  float oa[16][4];
#pragma unroll
  for (int a = 0; a < 16; a++)
#pragma unroll
    for (int r = 0; r < 4; r++) oa[a][r] = 0.f;

  float m0 = -3.0e38f, m1 = -3.0e38f, l0 = 0.f, l1 = 0.f;
  const int km0 = (q0 + rw + g < FR) ? FR : L_TOK;
  const int km1 = (q0 + rw + 8 + g < FR) ? FR : L_TOK;

  int qlast = q0 + 63; if (qlast >= L_TOK) qlast = L_TOK - 1;
  const int nt = (((qlast < FR) ? FR : L_TOK) + 63) >> 6;

  for (int kt = 0; kt < nt; kt++) {
    const int kb = kt * 64;
    const uint32_t ku = (kt & 1) ? k1_u : k0_u;
    asm volatile("cp.async.wait_group 0;");
    __syncthreads();

    load_tile(v, vb_u, kb);
    asm volatile("cp.async.commit_group;");
    const bool pk = (kt + 1 < nt);
    if (pk) {
      load_tile(k, ((kt + 1) & 1) ? k1_u : k0_u, kb + 64);
      asm volatile("cp.async.commit_group;");
    }

    // ---- S = Q K^T ----
    float s_[8][4];
#pragma unroll
    for (int a = 0; a < 8; a++)
#pragma unroll
      for (int r = 0; r < 4; r++) s_[a][r] = 0.f;

#pragma unroll
    for (int k16 = 0; k16 < 8; k16++) {
      const int kk = k16 * 16;
      unsigned av[4], bv[4][4];
      ldsm4(av, qs_u + ((rw + ar) * 136 + kk + aklo) * 2);
#pragma unroll
      for (int bn = 0; bn < 4; bn++)
        ldsm4(bv[bn], ku + ((16 * bn + br) * 136 + kk + bklo) * 2);
#pragma unroll
      for (int a = 0; a < 8; a++)
        mma_f16(s_[a], av, (a & 1) ? (bv[a >> 1] + 2) : bv[a >> 1]);
    }

    // ---- scale + mask ----
#pragma unroll
    for (int a = 0; a < 8; a++) {
      int cb = kb + 8 * a + 2 * t4;
      s_[a][0] = (cb     < km0) ? s_[a][0] * SCALE_F : -3.0e38f;
      s_[a][1] = (cb + 1 < km0) ? s_[a][1] * SCALE_F : -3.0e38f;
      s_[a][2] = (cb     < km1) ? s_[a][2] * SCALE_F : -3.0e38f;
      s_[a][3] = (cb + 1 < km1) ? s_[a][3] * SCALE_F : -3.0e38f;
    }

    // ---- warp-local softmax ----
    float mx0 = -3.0e38f, mx1 = -3.0e38f;
#pragma unroll
    for (int a = 0; a < 8; a++) {
      mx0 = fmaxf(mx0, fmaxf(s_[a][0], s_[a][1]));
      mx1 = fmaxf(mx1, fmaxf(s_[a][2], s_[a][3]));
    }
    mx0 = fmaxf(mx0, __shfl_xor_sync(0xffffffffu, mx0, 1));
    mx0 = fmaxf(mx0, __shfl_xor_sync(0xffffffffu, mx0, 2));
    mx1 = fmaxf(mx1, __shfl_xor_sync(0xffffffffu, mx1, 1));
    mx1 = fmaxf(mx1, __shfl_xor_sync(0xffffffffu, mx1, 2));
    const float mn0 = fmaxf(m0, mx0), mn1 = fmaxf(m1, mx1);
    const float cr0 = __expf(m0 - mn0), cr1 = __expf(m1 - mn1);
    m0 = mn0; m1 = mn1;

    unsigned pa[4][4];
    float sl0 = 0.f, sl1 = 0.f;
#pragma unroll
    for (int jk = 0; jk < 4; jk++) {
#pragma unroll
      for (int hh = 0; hh < 2; hh++) {
        const int a = 2 * jk + hh;
        float e0 = __expf(s_[a][0] - mn0);
        float e1 = __expf(s_[a][1] - mn0);
        float e2 = __expf(s_[a][2] - mn1);
        float e3 = __expf(s_[a][3] - mn1);
        sl0 += e0 + e1; sl1 += e2 + e3;
        pa[jk][2 * hh] = h2u(e0, e1);
        pa[jk][2 * hh + 1] = h2u(e2, e3);
      }
    }
    sl0 += __shfl_xor_sync(0xffffffffu, sl0, 1);
    sl0 += __shfl_xor_sync(0xffffffffu, sl0, 2);
    sl1 += __shfl_xor_sync(0xffffffffu, sl1, 1);
    sl1 += __shfl_xor_sync(0xffffffffu, sl1, 2);
    l0 = l0 * cr0 + sl0;
    l1 = l1 * cr1 + sl1;

#pragma unroll
    for (int a = 0; a < 16; a++) {
      oa[a][0] *= cr0; oa[a][1] *= cr0;
      oa[a][2] *= cr1; oa[a][3] *= cr1;
    }

    if (pk) asm volatile("cp.async.wait_group 1;");
    else    asm volatile("cp.async.wait_group 0;");
    __syncthreads();

    // ---- O += P V ----
#pragma unroll
    for (int jk = 0; jk < 4; jk++) {
      const int kk = jk * 16;
      unsigned bv[8][4];
#pragma unroll
      for (int nb = 0; nb < 8; nb++)
        ldsm4t(bv[nb], vb_u + ((kk + vrow) * 136 + 16 * nb + vcol) * 2);
#pragma unroll
      for (int na = 0; na < 16; na++)
        mma_f16(oa[na], pa[jk], (na & 1) ? (bv[na >> 1] + 2) : bv[na >> 1]);
    }
  }

  // ---- epilogue ----
  const float inv0 = 1.0f / l0, inv1 = 1.0f / l1;
  const int gr0 = q0 + rw + g, gr1 = gr0 + 8;
#pragma unroll
  for (int na = 0; na < 16; na++) {
    const int col = h * HD + 8 * na + 2 * t4;
    if (gr0 < L_TOK)
      *(__half2*)(o + (size_t)gr0 * DIM + col) =
          __floats2half2_rn(oa[na][0] * inv0, oa[na][1] * inv0);
    if (gr1 < L_TOK)
      *(__half2*)(o + (size_t)gr1 * DIM + col) =
          __floats2half2_rn(oa[na][2] * inv1, oa[na][3] * inv1);
  }
}

// ---------------- launch ----------------
extern "C" void kernel_launch(void* const* d_in, const int* in_sizes, int n_in,
                              void* d_out, int out_size) {
  const float* x  = (const float*)d_in[0];
  const float* wq = (const float*)d_in[1];
  const float* wk = (const float*)d_in[2];
  const float* wv = (const float*)d_in[3];
  const float* wo = (const float*)d_in[4];
  const float* bq = (const float*)d_in[5];
  const float* bk = (const float*)d_in[6];
  const float* bv = (const float*)d_in[7];
  const float* bo = (const float*)d_in[8];
  const float* gq = (const float*)d_in[9];
  const float* gk = (const float*)d_in[10];
  const float* fc = (const float*)d_in[11];
  const float* fs = (const float*)d_in[12];
  float* out = (float*)d_out;

  __half *qb, *kb, *vb, *ab, *xh, *wqkv, *wot;
  cudaGetSymbolAddress((void**)&qb, g_q);
  cudaGetSymbolAddress((void**)&kb, g_k);
  cudaGetSymbolAddress((void**)&vb, g_v);
  cudaGetSymbolAddress((void**)&ab, g_a);
  cudaGetSymbolAddress((void**)&xh, g_xh);
  cudaGetSymbolAddress((void**)&wqkv, g_wqkv);
  cudaGetSymbolAddress((void**)&wot, g_wo);

  cudaFuncSetAttribute(gemm_f16<1>, cudaFuncAttributeMaxDynamicSharedMemorySize, GEMM_SMEM);
  cudaFuncSetAttribute(gemm_f16<0>, cudaFuncAttributeMaxDynamicSharedMemorySize, GEMM_SMEM);
  cudaFuncSetAttribute(attn_f16_kernel, cudaFuncAttributeMaxDynamicSharedMemorySize, ATT_SMEM);

  // one conversion launch: z 0..3 = weight transposes, z=4 = x fp32->fp16
  cvt_all_kernel<<<dim3(DIM / 32, DIM / 32, 5), 256>>>(
      x, wq, wk, wv, wo, xh, wqkv, wot);

  gemm_f16<1><<<dim3(3 * DIM / 256, (L_TOK + 63) / 64), 256, GEMM_SMEM>>>(
      xh, wqkv, bq, bk, bv, nullptr, qb, kb, vb, L_TOK);

  rms_rope_kernel<<<L_TOK, 512>>>(qb, kb, gq, gk, fc, fs);

  attn_f16_kernel<<<dim3((L_TOK + 63) / 64, NH), 128, ATT_SMEM>>>(qb, kb, vb, ab);

  gemm_f16<0><<<dim3(DIM / 256, (L_TOK + 63) / 64), 256, GEMM_SMEM>>>(
      ab, wot, bo, nullptr, nullptr, out, nullptr, nullptr, nullptr, L_TOK);
}

// round 12
// speedup vs baseline: 1.0228x; 1.0070x over previous
#include <cuda_runtime.h>
#include <cuda_fp16.h>
#include <cstdint>

#define L_TOK 3120
#define DIM 1536
#define NH 12
#define HD 128
#define FR 1560
#define SCALE_F 0.08838834764831845f

// ---------------- scratch ----------------
__device__ __align__(16) __half g_q[L_TOK * DIM];       // Q fp16 (post rms_rope)
__device__ __align__(16) __half g_k[L_TOK * DIM];
__device__ __align__(16) __half g_v[L_TOK * DIM];       // V fp16, plain [L][DIM]
__device__ __align__(16) __half g_a[L_TOK * DIM];       // attn out fp16
__device__ __align__(16) __half g_xh[L_TOK * DIM];      // x fp16
__device__ __align__(16) __half g_wqkv[3 * DIM * DIM];  // [4608][1536] fp16 (W^T)
__device__ __align__(16) __half g_wo[DIM * DIM];        // wo^T fp16

// ---------------- helpers ----------------
__device__ __forceinline__ void mma_f16(float c[4], const unsigned a[4],
                                        const unsigned* b) {
  asm volatile(
      "mma.sync.aligned.m16n8k16.row.col.f32.f16.f16.f32 "
      "{%0,%1,%2,%3},{%4,%5,%6,%7},{%8,%9},{%0,%1,%2,%3};"
      : "+f"(c[0]), "+f"(c[1]), "+f"(c[2]), "+f"(c[3])
      : "r"(a[0]), "r"(a[1]), "r"(a[2]), "r"(a[3]), "r"(b[0]), "r"(b[1]));
}
__device__ __forceinline__ void ldsm4(unsigned r[4], uint32_t addr) {
  asm volatile(
      "ldmatrix.sync.aligned.m8n8.x4.shared.b16 {%0,%1,%2,%3}, [%4];"
      : "=r"(r[0]), "=r"(r[1]), "=r"(r[2]), "=r"(r[3]) : "r"(addr));
}
__device__ __forceinline__ void ldsm4t(unsigned r[4], uint32_t addr) {
  asm volatile(
      "ldmatrix.sync.aligned.m8n8.x4.trans.shared.b16 {%0,%1,%2,%3}, [%4];"
      : "=r"(r[0]), "=r"(r[1]), "=r"(r[2]), "=r"(r[3]) : "r"(addr));
}
__device__ __forceinline__ uint32_t smem_u32(const void* p) {
  uint32_t a;
  asm("{ .reg .u64 t; cvta.to.shared.u64 t, %1; cvt.u32.u64 %0, t; }"
      : "=r"(a) : "l"(p));
  return a;
}
__device__ __forceinline__ unsigned h2u(float a, float b) {
  __half2 h = __floats2half2_rn(a, b);
  return *(unsigned*)&h;
}

// ---------------- merged cvt kernel ----------------
__global__ __launch_bounds__(256) void cvt_all_kernel(
    const float* __restrict__ x, const float* __restrict__ w0,
    const float* __restrict__ w1, const float* __restrict__ w2,
    const float* __restrict__ w3, __half* __restrict__ xh,
    __half* __restrict__ qkv, __half* __restrict__ wot) {
  const int z = blockIdx.z;
  if (z == 4) {
    const int nblk = gridDim.x * gridDim.y;
    const int bid = blockIdx.y * gridDim.x + blockIdx.x;
    const int n4 = L_TOK * DIM / 4;
    for (int i = bid * 256 + threadIdx.x; i < n4; i += nblk * 256) {
      float4 v = *(const float4*)(x + 4 * (size_t)i);
      __half2* dp = (__half2*)(xh + 4 * (size_t)i);
      dp[0] = __floats2half2_rn(v.x, v.y);
      dp[1] = __floats2half2_rn(v.z, v.w);
    }
    return;
  }
  __shared__ float tile[32][33];
  const float* src = (z == 0) ? w0 : (z == 1) ? w1 : (z == 2) ? w2 : w3;
  __half* dst = (z == 3) ? wot : (qkv + (size_t)z * DIM * DIM);
  const int k0 = blockIdx.x * 32, n0 = blockIdx.y * 32;
  const int xx = threadIdx.x & 31, yy = threadIdx.x >> 5;
#pragma unroll
  for (int i = 0; i < 4; i++)
    tile[yy + 8 * i][xx] = src[(size_t)(k0 + yy + 8 * i) * DIM + n0 + xx];
  __syncthreads();
#pragma unroll
  for (int i = 0; i < 4; i++)
    dst[(size_t)(n0 + yy + 8 * i) * DIM + k0 + xx] =
        __float2half(tile[xx][yy + 8 * i]);
}

// ---------------- fp16 GEMM (round-9/11 best config) ----------------
#define AST 40
#define A_HS (64 * AST)
#define B_HS (256 * AST)
#define NST 3
#define GEMM_SMEM (NST * (A_HS + B_HS) * 2)

template <int QKV>
__global__ __launch_bounds__(256, 2) void gemm_f16(
    const __half* __restrict__ A, const __half* __restrict__ Wt,
    const float* __restrict__ b0, const float* __restrict__ b1,
    const float* __restrict__ b2, float* __restrict__ Cf,
    __half* __restrict__ H0, __half* __restrict__ H1,
    __half* __restrict__ H2, int M) {
  extern __shared__ __half smh[];
  const uint32_t sm_u = smem_u32(smh);

  const int t = threadIdx.x;
  const int m0 = blockIdx.y * 64;
  const int n0g = blockIdx.x * 256;
  const int warp = t >> 5, lane = t & 31;
  const int wm = (warp & 1) * 32;
  const int wn = (warp >> 1) * 64;
  const int g = lane >> 2, t4 = lane & 3;
  const int ar = lane & 15, aklo = (lane & 16) >> 1;
  const int br = (lane & 7) + ((lane & 16) >> 1), bklo = lane & 8;

  float c[2][8][4];
#pragma unroll
  for (int i = 0; i < 2; i++)
#pragma unroll
    for (int j = 0; j < 8; j++)
#pragma unroll
      for (int r = 0; r < 4; r++) c[i][j][r] = 0.f;

  auto prefetch = [&](int buf, int k0) {
    __half* asb = smh + buf * (A_HS + B_HS);
    __half* bsb = asb + A_HS;
    {
      int row = t >> 2, c8 = (t & 3) << 3;
      int gr = m0 + row;
      if (gr >= M) gr = M - 1;
      unsigned dst = (unsigned)__cvta_generic_to_shared(asb + row * AST + c8);
      asm volatile("cp.async.cg.shared.global [%0], [%1], 16;" ::"r"(dst),
                   "l"(A + (size_t)gr * DIM + k0 + c8));
    }
#pragma unroll
    for (int i = 0; i < 4; i++) {
      int idx = t + 256 * i;
      int row = idx >> 2, c8 = (idx & 3) << 3;
      unsigned dst = (unsigned)__cvta_generic_to_shared(bsb + row * AST + c8);
      asm volatile("cp.async.cg.shared.global [%0], [%1], 16;" ::"r"(dst),
                   "l"(Wt + (size_t)(n0g + row) * DIM + k0 + c8));
    }
  };

  prefetch(0, 0);
  asm volatile("cp.async.commit_group;");
  prefetch(1, 32);
  asm volatile("cp.async.commit_group;");

  const int KT = DIM / 32;
  for (int kt = 0; kt < KT; kt++) {
    const int s = kt % 3;
    asm volatile("cp.async.wait_group 1;");
    __syncthreads();

    const uint32_t au = sm_u + s * (A_HS + B_HS) * 2;
    const uint32_t bu = au + A_HS * 2;

#pragma unroll
    for (int kk = 0; kk < 32; kk += 16) {
      unsigned av[2][4], bv[4][4];
#pragma unroll
      for (int am = 0; am < 2; am++)
        ldsm4(av[am], au + ((wm + 16 * am + ar) * AST + kk + aklo) * 2);
#pragma unroll
      for (int bn = 0; bn < 4; bn++)
        ldsm4(bv[bn], bu + ((wn + 16 * bn + br) * AST + kk + bklo) * 2);
#pragma unroll
      for (int am = 0; am < 2; am++)
#pragma unroll
        for (int an = 0; an < 8; an++)
          mma_f16(c[am][an], av[am], (an & 1) ? (bv[an >> 1] + 2) : bv[an >> 1]);
    }

    if (kt + 2 < KT) prefetch((kt + 2) % 3, (kt + 2) * 32);
    asm volatile("cp.async.commit_group;");
  }

  // ---- epilogue ----
  int part = 0, ncol0 = n0g;
  const float* bias = b0;
  if (QKV) {
    part = n0g / DIM;
    ncol0 = n0g - part * DIM;
    bias = (part == 0) ? b0 : (part == 1) ? b1 : b2;
  }
  __half* H = QKV ? ((part == 0) ? H0 : (part == 1) ? H1 : H2) : (__half*)0;
#pragma unroll
  for (int am = 0; am < 2; am++) {
    const int r0 = m0 + wm + 16 * am + g;
    const int r1 = r0 + 8;
#pragma unroll
    for (int an = 0; an < 8; an++) {
      const int col = ncol0 + wn + 8 * an + 2 * t4;
      const float bb0 = bias[col], bb1 = bias[col + 1];
      if (!QKV) {
        if (r0 < M)
          *(float2*)(Cf + (size_t)r0 * DIM + col) =
              make_float2(c[am][an][0] + bb0, c[am][an][1] + bb1);
        if (r1 < M)
          *(float2*)(Cf + (size_t)r1 * DIM + col) =
              make_float2(c[am][an][2] + bb0, c[am][an][3] + bb1);
      } else {
        if (r0 < M)
          *(__half2*)(H + (size_t)r0 * DIM + col) =
              __floats2half2_rn(c[am][an][0] + bb0, c[am][an][1] + bb1);
        if (r1 < M)
          *(__half2*)(H + (size_t)r1 * DIM + col) =
              __floats2half2_rn(c[am][an][2] + bb0, c[am][an][3] + bb1);
      }
    }
  }
}

// ---------------- fused RMSNorm + RoPE (fp16 in/out), 512 thr ----------------
__global__ __launch_bounds__(512) void rms_rope_kernel(
    __half* __restrict__ qbuf, __half* __restrict__ kbuf,
    const float* __restrict__ gq, const float* __restrict__ gk,
    const float* __restrict__ cosp, const float* __restrict__ sinp) {
  const int l = blockIdx.x;
  const int half = threadIdx.x >> 8;
  __half* row = (half == 0) ? (qbuf + (size_t)l * DIM) : (kbuf + (size_t)l * DIM);
  const float* g = (half == 0) ? gq : gk;
  const int t = threadIdx.x & 255;

  float2 v[3], cs[3], gv[3];
  float ss = 0.f;
#pragma unroll
  for (int j = 0; j < 3; j++) {
    int p = t + 256 * j;
    v[j] = __half22float2(((const __half2*)row)[p]);
    int hd2 = p & 63;
    cs[j] = make_float2(cosp[l * 64 + hd2], sinp[l * 64 + hd2]);
    gv[j] = *(const float2*)(g + 2 * p);
    ss += v[j].x * v[j].x + v[j].y * v[j].y;
  }
#pragma unroll
  for (int off = 16; off > 0; off >>= 1)
    ss += __shfl_xor_sync(0xffffffffu, ss, off);
  __shared__ float red[2][8];
  if ((t & 31) == 0) red[half][t >> 5] = ss;
  __syncthreads();
  float tot = 0.f;
#pragma unroll
  for (int w = 0; w < 8; w++) tot += red[half][w];
  const float r = rsqrtf(tot * (1.0f / (float)DIM) + 1e-6f);

#pragma unroll
  for (int j = 0; j < 3; j++) {
    int p = t + 256 * j;
    float e = v[j].x * r * gv[j].x;
    float o = v[j].y * r * gv[j].y;
    ((__half2*)row)[p] =
        __floats2half2_rn(e * cs[j].x - o * cs[j].y, e * cs[j].y + o * cs[j].x);
  }
}

// ---------------- fp16 flash attention: BQ=128, 8 warps, occ 2 ----------
// Q[128][136] + K0/K1/V[64][136]. Warp = 16 query rows x 64 kv cols.
#define QT_H (128 * 136)
#define KT_H (64 * 136)
#define ATT_SMEM ((QT_H + 3 * KT_H) * 2)   // 87040 B

__global__ __launch_bounds__(256, 2) void attn_f16_kernel(
    const __half* __restrict__ q, const __half* __restrict__ k,
    const __half* __restrict__ v, __half* __restrict__ o) {
  extern __shared__ __half smh[];
  const uint32_t qs_u = smem_u32(smh);
  const uint32_t k0_u = qs_u + QT_H * 2;
  const uint32_t k1_u = k0_u + KT_H * 2;
  const uint32_t vb_u = k1_u + KT_H * 2;

  const int t = threadIdx.x, lane = t & 31, w = t >> 5;
  const int g = lane >> 2, t4 = lane & 3;
  const int q0 = (int)(gridDim.x - 1 - blockIdx.x) * 128;   // LPT
  const int h = blockIdx.y;
  const int rw = w * 16;
  const int ar = lane & 15, aklo = (lane & 16) >> 1;
  const int br = (lane & 7) + ((lane & 16) >> 1), bklo = lane & 8;
  const int vrow = lane & 15, vcol = (lane >> 4) << 3;

  // 64-row tile load (256 thr, 4 iters)
  auto load_kv = [&](const __half* src, uint32_t dst_u, int kb) {
#pragma unroll
    for (int i = 0; i < 4; i++) {
      int idx = t + 256 * i, r = idx >> 4, c8 = (idx & 15) << 3;
      int kr = kb + r;
      int sz = (kr < L_TOK) ? 16 : 0;
      if (kr >= L_TOK) kr = L_TOK - 1;
      asm volatile("cp.async.cg.shared.global [%0], [%1], 16, %2;" ::
                   "r"(dst_u + (uint32_t)(r * 136 + c8) * 2),
                   "l"(src + (size_t)kr * DIM + h * HD + c8), "r"(sz));
    }
  };

  // Q tile: 128 rows (8 iters)
#pragma unroll
  for (int i = 0; i < 8; i++) {
    int idx = t + 256 * i, r = idx >> 4, c8 = (idx & 15) << 3;
    int qr = q0 + r;
    int sz = (qr < L_TOK) ? 16 : 0;
    if (qr >= L_TOK) qr = L_TOK - 1;
    asm volatile("cp.async.cg.shared.global [%0], [%1], 16, %2;" ::
                 "r"(qs_u + (uint32_t)(r * 136 + c8) * 2),
                 "l"(q + (size_t)qr * DIM + h * HD + c8), "r"(sz));
  }
  load_kv(k, k0_u, 0);
  asm volatile("cp.async.commit_group;");

  float oa[16][4];
#pragma unroll
  for (int a = 0; a < 16; a++)
#pragma unroll
    for (int r = 0; r < 4; r++) oa[a][r] = 0.f;

  float m0 = -3.0e38f, m1 = -3.0e38f, l0 = 0.f, l1 = 0.f;
  const int km0 = (q0 + rw + g < FR) ? FR : L_TOK;
  const int km1 = (q0 + rw + 8 + g < FR) ? FR : L_TOK;

  int qlast = q0 + 127; if (qlast >= L_TOK) qlast = L_TOK - 1;
  const int nt = (((qlast < FR) ? FR : L_TOK) + 63) >> 6;

  for (int kt = 0; kt < nt; kt++) {
    const int kb = kt * 64;
    const uint32_t ku = (kt & 1) ? k1_u : k0_u;
    asm volatile("cp.async.wait_group 0;");
    __syncthreads();

    load_kv(v, vb_u, kb);
    asm volatile("cp.async.commit_group;");
    const bool pk = (kt + 1 < nt);
    if (pk) {
      load_kv(k, ((kt + 1) & 1) ? k1_u : k0_u, kb + 64);
      asm volatile("cp.async.commit_group;");
    }

    // ---- S = Q K^T : 16 rows x 64 cols per warp ----
    float s_[8][4];
#pragma unroll
    for (int a = 0; a < 8; a++)
#pragma unroll
      for (int r = 0; r < 4; r++) s_[a][r] = 0.f;

#pragma unroll
    for (int k16 = 0; k16 < 8; k16++) {
      const int kk = k16 * 16;
      unsigned av[4], bv[4][4];
      ldsm4(av, qs_u + ((rw + ar) * 136 + kk + aklo) * 2);
#pragma unroll
      for (int bn = 0; bn < 4; bn++)
        ldsm4(bv[bn], ku + ((16 * bn + br) * 136 + kk + bklo) * 2);
#pragma unroll
      for (int a = 0; a < 8; a++)
        mma_f16(s_[a], av, (a & 1) ? (bv[a >> 1] + 2) : bv[a >> 1]);
    }

    // ---- scale + mask ----
#pragma unroll
    for (int a = 0; a < 8; a++) {
      int cb = kb + 8 * a + 2 * t4;
      s_[a][0] = (cb     < km0) ? s_[a][0] * SCALE_F : -3.0e38f;
      s_[a][1] = (cb + 1 < km0) ? s_[a][1] * SCALE_F : -3.0e38f;
      s_[a][2] = (cb     < km1) ? s_[a][2] * SCALE_F : -3.0e38f;
      s_[a][3] = (cb + 1 < km1) ? s_[a][3] * SCALE_F : -3.0e38f;
    }

    // ---- warp-local softmax ----
    float mx0 = -3.0e38f, mx1 = -3.0e38f;
#pragma unroll
    for (int a = 0; a < 8; a++) {
      mx0 = fmaxf(mx0, fmaxf(s_[a][0], s_[a][1]));
      mx1 = fmaxf(mx1, fmaxf(s_[a][2], s_[a][3]));
    }
    mx0 = fmaxf(mx0, __shfl_xor_sync(0xffffffffu, mx0, 1));
    mx0 = fmaxf(mx0, __shfl_xor_sync(0xffffffffu, mx0, 2));
    mx1 = fmaxf(mx1, __shfl_xor_sync(0xffffffffu, mx1, 1));
    mx1 = fmaxf(mx1, __shfl_xor_sync(0xffffffffu, mx1, 2));
    const float mn0 = fmaxf(m0, mx0), mn1 = fmaxf(m1, mx1);
    const float cr0 = __expf(m0 - mn0), cr1 = __expf(m1 - mn1);
    m0 = mn0; m1 = mn1;

    unsigned pa[4][4];
    float sl0 = 0.f, sl1 = 0.f;
#pragma unroll
    for (int jk = 0; jk < 4; jk++) {
#pragma unroll
      for (int hh = 0; hh < 2; hh++) {
        const int a = 2 * jk + hh;
        float e0 = __expf(s_[a][0] - mn0);
        float e1 = __expf(s_[a][1] - mn0);
        float e2 = __expf(s_[a][2] - mn1);
        float e3 = __expf(s_[a][3] - mn1);
        sl0 += e0 + e1; sl1 += e2 + e3;
        pa[jk][2 * hh] = h2u(e0, e1);
        pa[jk][2 * hh + 1] = h2u(e2, e3);
      }
    }
    sl0 += __shfl_xor_sync(0xffffffffu, sl0, 1);
    sl0 += __shfl_xor_sync(0xffffffffu, sl0, 2);
    sl1 += __shfl_xor_sync(0xffffffffu, sl1, 1);
    sl1 += __shfl_xor_sync(0xffffffffu, sl1, 2);
    l0 = l0 * cr0 + sl0;
    l1 = l1 * cr1 + sl1;

#pragma unroll
    for (int a = 0; a < 16; a++) {
      oa[a][0] *= cr0; oa[a][1] *= cr0;
      oa[a][2] *= cr1; oa[a][3] *= cr1;
    }

    if (pk) asm volatile("cp.async.wait_group 1;");
    else    asm volatile("cp.async.wait_group 0;");
    __syncthreads();

    // ---- O += P V ----
#pragma unroll
    for (int jk = 0; jk < 4; jk++) {
      const int kk = jk * 16;
      unsigned bv[8][4];
#pragma unroll
      for (int nb = 0; nb < 8; nb++)
        ldsm4t(bv[nb], vb_u + ((kk + vrow) * 136 + 16 * nb + vcol) * 2);
#pragma unroll
      for (int na = 0; na < 16; na++)
        mma_f16(oa[na], pa[jk], (na & 1) ? (bv[na >> 1] + 2) : bv[na >> 1]);
    }
  }

  // ---- epilogue ----
  const float inv0 = 1.0f / l0, inv1 = 1.0f / l1;
  const int gr0 = q0 + rw + g, gr1 = gr0 + 8;
#pragma unroll
  for (int na = 0; na < 16; na++) {
    const int col = h * HD + 8 * na + 2 * t4;
    if (gr0 < L_TOK)
      *(__half2*)(o + (size_t)gr0 * DIM + col) =
          __floats2half2_rn(oa[na][0] * inv0, oa[na][1] * inv0);
    if (gr1 < L_TOK)
      *(__half2*)(o + (size_t)gr1 * DIM + col) =
          __floats2half2_rn(oa[na][2] * inv1, oa[na][3] * inv1);
  }
}

// ---------------- launch ----------------
extern "C" void kernel_launch(void* const* d_in, const int* in_sizes, int n_in,
                              void* d_out, int out_size) {
  const float* x  = (const float*)d_in[0];
  const float* wq = (const float*)d_in[1];
  const float* wk = (const float*)d_in[2];
  const float* wv = (const float*)d_in[3];
  const float* wo = (const float*)d_in[4];
  const float* bq = (const float*)d_in[5];
  const float* bk = (const float*)d_in[6];
  const float* bv = (const float*)d_in[7];
  const float* bo = (const float*)d_in[8];
  const float* gq = (const float*)d_in[9];
  const float* gk = (const float*)d_in[10];
  const float* fc = (const float*)d_in[11];
  const float* fs = (const float*)d_in[12];
  float* out = (float*)d_out;

  __half *qb, *kb, *vb, *ab, *xh, *wqkv, *wot;
  cudaGetSymbolAddress((void**)&qb, g_q);
  cudaGetSymbolAddress((void**)&kb, g_k);
  cudaGetSymbolAddress((void**)&vb, g_v);
  cudaGetSymbolAddress((void**)&ab, g_a);
  cudaGetSymbolAddress((void**)&xh, g_xh);
  cudaGetSymbolAddress((void**)&wqkv, g_wqkv);
  cudaGetSymbolAddress((void**)&wot, g_wo);

  cudaFuncSetAttribute(gemm_f16<1>, cudaFuncAttributeMaxDynamicSharedMemorySize, GEMM_SMEM);
  cudaFuncSetAttribute(gemm_f16<0>, cudaFuncAttributeMaxDynamicSharedMemorySize, GEMM_SMEM);
  cudaFuncSetAttribute(attn_f16_kernel, cudaFuncAttributeMaxDynamicSharedMemorySize, ATT_SMEM);

  cvt_all_kernel<<<dim3(DIM / 32, DIM / 32, 5), 256>>>(
      x, wq, wk, wv, wo, xh, wqkv, wot);

  gemm_f16<1><<<dim3(3 * DIM / 256, (L_TOK + 63) / 64), 256, GEMM_SMEM>>>(
      xh, wqkv, bq, bk, bv, nullptr, qb, kb, vb, L_TOK);

  rms_rope_kernel<<<L_TOK, 512>>>(qb, kb, gq, gk, fc, fs);

  // 25 q-blocks x 12 heads = 300 CTAs, occ 2 -> ~1 wave
  attn_f16_kernel<<<dim3((L_TOK + 127) / 128, NH), 256, ATT_SMEM>>>(qb, kb, vb, ab);

  gemm_f16<0><<<dim3(DIM / 256, (L_TOK + 63) / 64), 256, GEMM_SMEM>>>(
      ab, wot, bo, nullptr, nullptr, out, nullptr, nullptr, nullptr, L_TOK);
}

// round 13
// speedup vs baseline: 1.1481x; 1.1226x over previous
#include <cuda_runtime.h>
#include <cuda_fp16.h>
#include <cstdint>

#define L_TOK 3120
#define DIM 1536
#define NH 12
#define HD 128
#define FR 1560
#define SCALE_F 0.08838834764831845f
#define NQB 49                  // ceil(3120/64)
#define NUNITS (NQB * NH)       // 588
#define ATT_GRID 444            // 148 SM x occ 3

// ---------------- scratch ----------------
__device__ __align__(16) __half g_q[L_TOK * DIM];
__device__ __align__(16) __half g_k[L_TOK * DIM];
__device__ __align__(16) __half g_v[L_TOK * DIM];
__device__ __align__(16) __half g_a[L_TOK * DIM];
__device__ __align__(16) __half g_xh[L_TOK * DIM];
__device__ __align__(16) __half g_wqkv[3 * DIM * DIM];
__device__ __align__(16) __half g_wo[DIM * DIM];
__device__ int g_ctr;           // work-stealing counter (reset by rope kernel)

// ---------------- helpers ----------------
__device__ __forceinline__ void mma_f16(float c[4], const unsigned a[4],
                                        const unsigned* b) {
  asm volatile(
      "mma.sync.aligned.m16n8k16.row.col.f32.f16.f16.f32 "
      "{%0,%1,%2,%3},{%4,%5,%6,%7},{%8,%9},{%0,%1,%2,%3};"
      : "+f"(c[0]), "+f"(c[1]), "+f"(c[2]), "+f"(c[3])
      : "r"(a[0]), "r"(a[1]), "r"(a[2]), "r"(a[3]), "r"(b[0]), "r"(b[1]));
}
__device__ __forceinline__ void ldsm4(unsigned r[4], uint32_t addr) {
  asm volatile(
      "ldmatrix.sync.aligned.m8n8.x4.shared.b16 {%0,%1,%2,%3}, [%4];"
      : "=r"(r[0]), "=r"(r[1]), "=r"(r[2]), "=r"(r[3]) : "r"(addr));
}
__device__ __forceinline__ void ldsm4t(unsigned r[4], uint32_t addr) {
  asm volatile(
      "ldmatrix.sync.aligned.m8n8.x4.trans.shared.b16 {%0,%1,%2,%3}, [%4];"
      : "=r"(r[0]), "=r"(r[1]), "=r"(r[2]), "=r"(r[3]) : "r"(addr));
}
__device__ __forceinline__ uint32_t smem_u32(const void* p) {
  uint32_t a;
  asm("{ .reg .u64 t; cvta.to.shared.u64 t, %1; cvt.u32.u64 %0, t; }"
      : "=r"(a) : "l"(p));
  return a;
}
__device__ __forceinline__ unsigned h2u(float a, float b) {
  __half2 h = __floats2half2_rn(a, b);
  return *(unsigned*)&h;
}

// ---------------- merged cvt kernel ----------------
__global__ __launch_bounds__(256) void cvt_all_kernel(
    const float* __restrict__ x, const float* __restrict__ w0,
    const float* __restrict__ w1, const float* __restrict__ w2,
    const float* __restrict__ w3, __half* __restrict__ xh,
    __half* __restrict__ qkv, __half* __restrict__ wot) {
  const int z = blockIdx.z;
  if (z == 4) {
    const int nblk = gridDim.x * gridDim.y;
    const int bid = blockIdx.y * gridDim.x + blockIdx.x;
    const int n4 = L_TOK * DIM / 4;
    for (int i = bid * 256 + threadIdx.x; i < n4; i += nblk * 256) {
      float4 v = *(const float4*)(x + 4 * (size_t)i);
      __half2* dp = (__half2*)(xh + 4 * (size_t)i);
      dp[0] = __floats2half2_rn(v.x, v.y);
      dp[1] = __floats2half2_rn(v.z, v.w);
    }
    return;
  }
  __shared__ float tile[32][33];
  const float* src = (z == 0) ? w0 : (z == 1) ? w1 : (z == 2) ? w2 : w3;
  __half* dst = (z == 3) ? wot : (qkv + (size_t)z * DIM * DIM);
  const int k0 = blockIdx.x * 32, n0 = blockIdx.y * 32;
  const int xx = threadIdx.x & 31, yy = threadIdx.x >> 5;
#pragma unroll
  for (int i = 0; i < 4; i++)
    tile[yy + 8 * i][xx] = src[(size_t)(k0 + yy + 8 * i) * DIM + n0 + xx];
  __syncthreads();
#pragma unroll
  for (int i = 0; i < 4; i++)
    dst[(size_t)(n0 + yy + 8 * i) * DIM + k0 + xx] =
        __float2half(tile[xx][yy + 8 * i]);
}

// ---------------- fp16 GEMM (measured-best config) ----------------
#define AST 40
#define A_HS (64 * AST)
#define B_HS (256 * AST)
#define NST 3
#define GEMM_SMEM (NST * (A_HS + B_HS) * 2)

template <int QKV>
__global__ __launch_bounds__(256, 2) void gemm_f16(
    const __half* __restrict__ A, const __half* __restrict__ Wt,
    const float* __restrict__ b0, const float* __restrict__ b1,
    const float* __restrict__ b2, float* __restrict__ Cf,
    __half* __restrict__ H0, __half* __restrict__ H1,
    __half* __restrict__ H2, int M) {
  extern __shared__ __half smh[];
  const uint32_t sm_u = smem_u32(smh);

  const int t = threadIdx.x;
  const int m0 = blockIdx.y * 64;
  const int n0g = blockIdx.x * 256;
  const int warp = t >> 5, lane = t & 31;
  const int wm = (warp & 1) * 32;
  const int wn = (warp >> 1) * 64;
  const int g = lane >> 2, t4 = lane & 3;
  const int ar = lane & 15, aklo = (lane & 16) >> 1;
  const int br = (lane & 7) + ((lane & 16) >> 1), bklo = lane & 8;

  float c[2][8][4];
#pragma unroll
  for (int i = 0; i < 2; i++)
#pragma unroll
    for (int j = 0; j < 8; j++)
#pragma unroll
      for (int r = 0; r < 4; r++) c[i][j][r] = 0.f;

  auto prefetch = [&](int buf, int k0) {
    __half* asb = smh + buf * (A_HS + B_HS);
    __half* bsb = asb + A_HS;
    {
      int row = t >> 2, c8 = (t & 3) << 3;
      int gr = m0 + row;
      if (gr >= M) gr = M - 1;
      unsigned dst = (unsigned)__cvta_generic_to_shared(asb + row * AST + c8);
      asm volatile("cp.async.cg.shared.global [%0], [%1], 16;" ::"r"(dst),
                   "l"(A + (size_t)gr * DIM + k0 + c8));
    }
#pragma unroll
    for (int i = 0; i < 4; i++) {
      int idx = t + 256 * i;
      int row = idx >> 2, c8 = (idx & 3) << 3;
      unsigned dst = (unsigned)__cvta_generic_to_shared(bsb + row * AST + c8);
      asm volatile("cp.async.cg.shared.global [%0], [%1], 16;" ::"r"(dst),
                   "l"(Wt + (size_t)(n0g + row) * DIM + k0 + c8));
    }
  };

  prefetch(0, 0);
  asm volatile("cp.async.commit_group;");
  prefetch(1, 32);
  asm volatile("cp.async.commit_group;");

  const int KT = DIM / 32;
  for (int kt = 0; kt < KT; kt++) {
    const int s = kt % 3;
    asm volatile("cp.async.wait_group 1;");
    __syncthreads();

    const uint32_t au = sm_u + s * (A_HS + B_HS) * 2;
    const uint32_t bu = au + A_HS * 2;

#pragma unroll
    for (int kk = 0; kk < 32; kk += 16) {
      unsigned av[2][4], bv[4][4];
#pragma unroll
      for (int am = 0; am < 2; am++)
        ldsm4(av[am], au + ((wm + 16 * am + ar) * AST + kk + aklo) * 2);
#pragma unroll
      for (int bn = 0; bn < 4; bn++)
        ldsm4(bv[bn], bu + ((wn + 16 * bn + br) * AST + kk + bklo) * 2);
#pragma unroll
      for (int am = 0; am < 2; am++)
#pragma unroll
        for (int an = 0; an < 8; an++)
          mma_f16(c[am][an], av[am], (an & 1) ? (bv[an >> 1] + 2) : bv[an >> 1]);
    }

    if (kt + 2 < KT) prefetch((kt + 2) % 3, (kt + 2) * 32);
    asm volatile("cp.async.commit_group;");
  }

  // ---- epilogue ----
  int part = 0, ncol0 = n0g;
  const float* bias = b0;
  if (QKV) {
    part = n0g / DIM;
    ncol0 = n0g - part * DIM;
    bias = (part == 0) ? b0 : (part == 1) ? b1 : b2;
  }
  __half* H = QKV ? ((part == 0) ? H0 : (part == 1) ? H1 : H2) : (__half*)0;
#pragma unroll
  for (int am = 0; am < 2; am++) {
    const int r0 = m0 + wm + 16 * am + g;
    const int r1 = r0 + 8;
#pragma unroll
    for (int an = 0; an < 8; an++) {
      const int col = ncol0 + wn + 8 * an + 2 * t4;
      const float bb0 = bias[col], bb1 = bias[col + 1];
      if (!QKV) {
        if (r0 < M)
          *(float2*)(Cf + (size_t)r0 * DIM + col) =
              make_float2(c[am][an][0] + bb0, c[am][an][1] + bb1);
        if (r1 < M)
          *(float2*)(Cf + (size_t)r1 * DIM + col) =
              make_float2(c[am][an][2] + bb0, c[am][an][3] + bb1);
      } else {
        if (r0 < M)
          *(__half2*)(H + (size_t)r0 * DIM + col) =
              __floats2half2_rn(c[am][an][0] + bb0, c[am][an][1] + bb1);
        if (r1 < M)
          *(__half2*)(H + (size_t)r1 * DIM + col) =
              __floats2half2_rn(c[am][an][2] + bb0, c[am][an][3] + bb1);
      }
    }
  }
}

// ---------------- fused RMSNorm + RoPE (fp16), resets work counter --------
__global__ __launch_bounds__(512) void rms_rope_kernel(
    __half* __restrict__ qbuf, __half* __restrict__ kbuf,
    const float* __restrict__ gq, const float* __restrict__ gk,
    const float* __restrict__ cosp, const float* __restrict__ sinp) {
  if (blockIdx.x == 0 && threadIdx.x == 0) g_ctr = ATT_GRID;  // for attn stealing
  const int l = blockIdx.x;
  const int half = threadIdx.x >> 8;
  __half* row = (half == 0) ? (qbuf + (size_t)l * DIM) : (kbuf + (size_t)l * DIM);
  const float* g = (half == 0) ? gq : gk;
  const int t = threadIdx.x & 255;

  float2 v[3], cs[3], gv[3];
  float ss = 0.f;
#pragma unroll
  for (int j = 0; j < 3; j++) {
    int p = t + 256 * j;
    v[j] = __half22float2(((const __half2*)row)[p]);
    int hd2 = p & 63;
    cs[j] = make_float2(cosp[l * 64 + hd2], sinp[l * 64 + hd2]);
    gv[j] = *(const float2*)(g + 2 * p);
    ss += v[j].x * v[j].x + v[j].y * v[j].y;
  }
#pragma unroll
  for (int off = 16; off > 0; off >>= 1)
    ss += __shfl_xor_sync(0xffffffffu, ss, off);
  __shared__ float red[2][8];
  if ((t & 31) == 0) red[half][t >> 5] = ss;
  __syncthreads();
  float tot = 0.f;
#pragma unroll
  for (int w = 0; w < 8; w++) tot += red[half][w];
  const float r = rsqrtf(tot * (1.0f / (float)DIM) + 1e-6f);

#pragma unroll
  for (int j = 0; j < 3; j++) {
    int p = t + 256 * j;
    float e = v[j].x * r * gv[j].x;
    float o = v[j].y * r * gv[j].y;
    ((__half2*)row)[p] =
        __floats2half2_rn(e * cs[j].x - o * cs[j].y, e * cs[j].y + o * cs[j].x);
  }
}

// ---------------- persistent fp16 flash attention (work-stealing) ----------
// BQ=64, 4 warps, occ 3. Units = (qblock, head), LPT: descending qblock.
#define TILE_H (64 * 136)
#define ATT_SMEM (4 * TILE_H * 2)   // Q + K0 + K1 + V (68 KB)

__global__ __launch_bounds__(128, 3) void attn_f16_kernel(
    const __half* __restrict__ q, const __half* __restrict__ k,
    const __half* __restrict__ v, __half* __restrict__ o) {
  extern __shared__ __half smh[];
  __shared__ int s_next;
  const uint32_t qs_u = smem_u32(smh);
  const uint32_t k0_u = qs_u + TILE_H * 2;
  const uint32_t k1_u = k0_u + TILE_H * 2;
  const uint32_t vb_u = k1_u + TILE_H * 2;

  const int t = threadIdx.x, lane = t & 31, w = t >> 5;
  const int g = lane >> 2, t4 = lane & 3;
  const int rw = w * 16;
  const int ar = lane & 15, aklo = (lane & 16) >> 1;
  const int br = (lane & 7) + ((lane & 16) >> 1), bklo = lane & 8;
  const int vrow = lane & 15, vcol = (lane >> 4) << 3;

  int unit = blockIdx.x;

  while (unit < NUNITS) {
    const int ub = unit / NH;
    const int h = unit - ub * NH;
    const int blk = NQB - 1 - ub;          // LPT: long blocks first
    const int q0 = blk * 64;

    auto load_tile = [&](const __half* src, uint32_t dst_u, int kb) {
#pragma unroll
      for (int i = 0; i < 8; i++) {
        int idx = t + 128 * i, r = idx >> 4, c8 = (idx & 15) << 3;
        int kr = kb + r;
        int sz = (kr < L_TOK) ? 16 : 0;
        if (kr >= L_TOK) kr = L_TOK - 1;
        asm volatile("cp.async.cg.shared.global [%0], [%1], 16, %2;" ::
                     "r"(dst_u + (uint32_t)(r * 136 + c8) * 2),
                     "l"(src + (size_t)kr * DIM + h * HD + c8), "r"(sz));
      }
    };

    load_tile(q, qs_u, q0);
    load_tile(k, k0_u, 0);
    asm volatile("cp.async.commit_group;");

    float oa[16][4];
#pragma unroll
    for (int a = 0; a < 16; a++)
#pragma unroll
      for (int r = 0; r < 4; r++) oa[a][r] = 0.f;

    float m0 = -3.0e38f, m1 = -3.0e38f, l0 = 0.f, l1 = 0.f;
    const int km0 = (q0 + rw + g < FR) ? FR : L_TOK;
    const int km1 = (q0 + rw + 8 + g < FR) ? FR : L_TOK;

    int qlast = q0 + 63; if (qlast >= L_TOK) qlast = L_TOK - 1;
    const int nt = (((qlast < FR) ? FR : L_TOK) + 63) >> 6;

    for (int kt = 0; kt < nt; kt++) {
      const int kb = kt * 64;
      const uint32_t ku = (kt & 1) ? k1_u : k0_u;
      asm volatile("cp.async.wait_group 0;");
      __syncthreads();

      load_tile(v, vb_u, kb);
      asm volatile("cp.async.commit_group;");
      const bool pk = (kt + 1 < nt);
      if (pk) {
        load_tile(k, ((kt + 1) & 1) ? k1_u : k0_u, kb + 64);
        asm volatile("cp.async.commit_group;");
      }

      // ---- S = Q K^T ----
      float s_[8][4];
#pragma unroll
      for (int a = 0; a < 8; a++)
#pragma unroll
        for (int r = 0; r < 4; r++) s_[a][r] = 0.f;

#pragma unroll
      for (int k16 = 0; k16 < 8; k16++) {
        const int kk = k16 * 16;
        unsigned av[4], bv[4][4];
        ldsm4(av, qs_u + ((rw + ar) * 136 + kk + aklo) * 2);
#pragma unroll
        for (int bn = 0; bn < 4; bn++)
          ldsm4(bv[bn], ku + ((16 * bn + br) * 136 + kk + bklo) * 2);
#pragma unroll
        for (int a = 0; a < 8; a++)
          mma_f16(s_[a], av, (a & 1) ? (bv[a >> 1] + 2) : bv[a >> 1]);
      }

      // ---- scale + mask ----
#pragma unroll
      for (int a = 0; a < 8; a++) {
        int cb = kb + 8 * a + 2 * t4;
        s_[a][0] = (cb     < km0) ? s_[a][0] * SCALE_F : -3.0e38f;
        s_[a][1] = (cb + 1 < km0) ? s_[a][1] * SCALE_F : -3.0e38f;
        s_[a][2] = (cb     < km1) ? s_[a][2] * SCALE_F : -3.0e38f;
        s_[a][3] = (cb + 1 < km1) ? s_[a][3] * SCALE_F : -3.0e38f;
      }

      // ---- warp-local softmax ----
      float mx0 = -3.0e38f, mx1 = -3.0e38f;
#pragma unroll
      for (int a = 0; a < 8; a++) {
        mx0 = fmaxf(mx0, fmaxf(s_[a][0], s_[a][1]));
        mx1 = fmaxf(mx1, fmaxf(s_[a][2], s_[a][3]));
      }
      mx0 = fmaxf(mx0, __shfl_xor_sync(0xffffffffu, mx0, 1));
      mx0 = fmaxf(mx0, __shfl_xor_sync(0xffffffffu, mx0, 2));
      mx1 = fmaxf(mx1, __shfl_xor_sync(0xffffffffu, mx1, 1));
      mx1 = fmaxf(mx1, __shfl_xor_sync(0xffffffffu, mx1, 2));
      const float mn0 = fmaxf(m0, mx0), mn1 = fmaxf(m1, mx1);
      const float cr0 = __expf(m0 - mn0), cr1 = __expf(m1 - mn1);
      m0 = mn0; m1 = mn1;

      unsigned pa[4][4];
      float sl0 = 0.f, sl1 = 0.f;
#pragma unroll
      for (int jk = 0; jk < 4; jk++) {
#pragma unroll
        for (int hh = 0; hh < 2; hh++) {
          const int a = 2 * jk + hh;
          float e0 = __expf(s_[a][0] - mn0);
          float e1 = __expf(s_[a][1] - mn0);
          float e2 = __expf(s_[a][2] - mn1);
          float e3 = __expf(s_[a][3] - mn1);
          sl0 += e0 + e1; sl1 += e2 + e3;
          pa[jk][2 * hh] = h2u(e0, e1);
          pa[jk][2 * hh + 1] = h2u(e2, e3);
        }
      }
      sl0 += __shfl_xor_sync(0xffffffffu, sl0, 1);
      sl0 += __shfl_xor_sync(0xffffffffu, sl0, 2);
      sl1 += __shfl_xor_sync(0xffffffffu, sl1, 1);
      sl1 += __shfl_xor_sync(0xffffffffu, sl1, 2);
      l0 = l0 * cr0 + sl0;
      l1 = l1 * cr1 + sl1;

#pragma unroll
      for (int a = 0; a < 16; a++) {
        oa[a][0] *= cr0; oa[a][1] *= cr0;
        oa[a][2] *= cr1; oa[a][3] *= cr1;
      }

      if (pk) asm volatile("cp.async.wait_group 1;");
      else    asm volatile("cp.async.wait_group 0;");
      __syncthreads();

      // ---- O += P V ----
#pragma unroll
      for (int jk = 0; jk < 4; jk++) {
        const int kk = jk * 16;
        unsigned bv[8][4];
#pragma unroll
        for (int nb = 0; nb < 8; nb++)
          ldsm4t(bv[nb], vb_u + ((kk + vrow) * 136 + 16 * nb + vcol) * 2);
#pragma unroll
        for (int na = 0; na < 16; na++)
          mma_f16(oa[na], pa[jk], (na & 1) ? (bv[na >> 1] + 2) : bv[na >> 1]);
      }
    }

    // ---- unit epilogue ----
    const float inv0 = 1.0f / l0, inv1 = 1.0f / l1;
    const int gr0 = q0 + rw + g, gr1 = gr0 + 8;
#pragma unroll
    for (int na = 0; na < 16; na++) {
      const int col = h * HD + 8 * na + 2 * t4;
      if (gr0 < L_TOK)
        *(__half2*)(o + (size_t)gr0 * DIM + col) =
            __floats2half2_rn(oa[na][0] * inv0, oa[na][1] * inv0);
      if (gr1 < L_TOK)
        *(__half2*)(o + (size_t)gr1 * DIM + col) =
            __floats2half2_rn(oa[na][2] * inv1, oa[na][3] * inv1);
    }

    // ---- steal next unit ----
    if (t == 0) s_next = atomicAdd(&g_ctr, 1);
    __syncthreads();
    unit = s_next;
    __syncthreads();           // s_next stable before next iteration's write
  }
}

// ---------------- launch ----------------
extern "C" void kernel_launch(void* const* d_in, const int* in_sizes, int n_in,
                              void* d_out, int out_size) {
  const float* x  = (const float*)d_in[0];
  const float* wq = (const float*)d_in[1];
  const float* wk = (const float*)d_in[2];
  const float* wv = (const float*)d_in[3];
  const float* wo = (const float*)d_in[4];
  const float* bq = (const float*)d_in[5];
  const float* bk = (const float*)d_in[6];
  const float* bv = (const float*)d_in[7];
  const float* bo = (const float*)d_in[8];
  const float* gq = (const float*)d_in[9];
  const float* gk = (const float*)d_in[10];
  const float* fc = (const float*)d_in[11];
  const float* fs = (const float*)d_in[12];
  float* out = (float*)d_out;

  __half *qb, *kb, *vb, *ab, *xh, *wqkv, *wot;
  cudaGetSymbolAddress((void**)&qb, g_q);
  cudaGetSymbolAddress((void**)&kb, g_k);
  cudaGetSymbolAddress((void**)&vb, g_v);
  cudaGetSymbolAddress((void**)&ab, g_a);
  cudaGetSymbolAddress((void**)&xh, g_xh);
  cudaGetSymbolAddress((void**)&wqkv, g_wqkv);
  cudaGetSymbolAddress((void**)&wot, g_wo);

  cudaFuncSetAttribute(gemm_f16<1>, cudaFuncAttributeMaxDynamicSharedMemorySize, GEMM_SMEM);
  cudaFuncSetAttribute(gemm_f16<0>, cudaFuncAttributeMaxDynamicSharedMemorySize, GEMM_SMEM);
  cudaFuncSetAttribute(attn_f16_kernel, cudaFuncAttributeMaxDynamicSharedMemorySize, ATT_SMEM);

  cvt_all_kernel<<<dim3(DIM / 32, DIM / 32, 5), 256>>>(
      x, wq, wk, wv, wo, xh, wqkv, wot);

  gemm_f16<1><<<dim3(3 * DIM / 256, (L_TOK + 63) / 64), 256, GEMM_SMEM>>>(
      xh, wqkv, bq, bk, bv, nullptr, qb, kb, vb, L_TOK);

  rms_rope_kernel<<<L_TOK, 512>>>(qb, kb, gq, gk, fc, fs);

  attn_f16_kernel<<<ATT_GRID, 128, ATT_SMEM>>>(qb, kb, vb, ab);

  gemm_f16<0><<<dim3(DIM / 256, (L_TOK + 63) / 64), 256, GEMM_SMEM>>>(
      ab, wot, bo, nullptr, nullptr, out, nullptr, nullptr, nullptr, L_TOK);
}

// round 14
// speedup vs baseline: 1.1541x; 1.0052x over previous
#include <cuda_runtime.h>
#include <cuda_fp16.h>
#include <cstdint>

#define L_TOK 3120
#define DIM 1536
#define NH 12
#define HD 128
#define FR 1560
#define SCALE_F 0.08838834764831845f
#define NQB 49                  // ceil(3120/64)
#define NUNITS (NQB * NH)       // 588
#define ATT_GRID 444            // 148 SM x occ 3

// ---------------- scratch ----------------
__device__ __align__(16) __half g_q[L_TOK * DIM];
__device__ __align__(16) __half g_k[L_TOK * DIM];
__device__ __align__(16) __half g_v[L_TOK * DIM];
__device__ __align__(16) __half g_a[L_TOK * DIM];
__device__ __align__(16) __half g_xh[L_TOK * DIM];
__device__ __align__(16) __half g_wqkv[3 * DIM * DIM];
__device__ __align__(16) __half g_wo[DIM * DIM];
__device__ int g_ctr;           // work-stealing counter (reset by rope kernel)

// ---------------- helpers ----------------
__device__ __forceinline__ void mma_f16(float c[4], const unsigned a[4],
                                        const unsigned* b) {
  asm volatile(
      "mma.sync.aligned.m16n8k16.row.col.f32.f16.f16.f32 "
      "{%0,%1,%2,%3},{%4,%5,%6,%7},{%8,%9},{%0,%1,%2,%3};"
      : "+f"(c[0]), "+f"(c[1]), "+f"(c[2]), "+f"(c[3])
      : "r"(a[0]), "r"(a[1]), "r"(a[2]), "r"(a[3]), "r"(b[0]), "r"(b[1]));
}
__device__ __forceinline__ void ldsm4(unsigned r[4], uint32_t addr) {
  asm volatile(
      "ldmatrix.sync.aligned.m8n8.x4.shared.b16 {%0,%1,%2,%3}, [%4];"
      : "=r"(r[0]), "=r"(r[1]), "=r"(r[2]), "=r"(r[3]) : "r"(addr));
}
__device__ __forceinline__ void ldsm4t(unsigned r[4], uint32_t addr) {
  asm volatile(
      "ldmatrix.sync.aligned.m8n8.x4.trans.shared.b16 {%0,%1,%2,%3}, [%4];"
      : "=r"(r[0]), "=r"(r[1]), "=r"(r[2]), "=r"(r[3]) : "r"(addr));
}
__device__ __forceinline__ uint32_t smem_u32(const void* p) {
  uint32_t a;
  asm("{ .reg .u64 t; cvta.to.shared.u64 t, %1; cvt.u32.u64 %0, t; }"
      : "=r"(a) : "l"(p));
  return a;
}
__device__ __forceinline__ unsigned h2u(float a, float b) {
  __half2 h = __floats2half2_rn(a, b);
  return *(unsigned*)&h;
}

// ---------------- merged cvt kernel ----------------
__global__ __launch_bounds__(256) void cvt_all_kernel(
    const float* __restrict__ x, const float* __restrict__ w0,
    const float* __restrict__ w1, const float* __restrict__ w2,
    const float* __restrict__ w3, __half* __restrict__ xh,
    __half* __restrict__ qkv, __half* __restrict__ wot) {
  const int z = blockIdx.z;
  if (z == 4) {
    const int nblk = gridDim.x * gridDim.y;
    const int bid = blockIdx.y * gridDim.x + blockIdx.x;
    const int n4 = L_TOK * DIM / 4;
    for (int i = bid * 256 + threadIdx.x; i < n4; i += nblk * 256) {
      float4 v = *(const float4*)(x + 4 * (size_t)i);
      __half2* dp = (__half2*)(xh + 4 * (size_t)i);
      dp[0] = __floats2half2_rn(v.x, v.y);
      dp[1] = __floats2half2_rn(v.z, v.w);
    }
    return;
  }
  __shared__ float tile[32][33];
  const float* src = (z == 0) ? w0 : (z == 1) ? w1 : (z == 2) ? w2 : w3;
  __half* dst = (z == 3) ? wot : (qkv + (size_t)z * DIM * DIM);
  const int k0 = blockIdx.x * 32, n0 = blockIdx.y * 32;
  const int xx = threadIdx.x & 31, yy = threadIdx.x >> 5;
#pragma unroll
  for (int i = 0; i < 4; i++)
    tile[yy + 8 * i][xx] = src[(size_t)(k0 + yy + 8 * i) * DIM + n0 + xx];
  __syncthreads();
#pragma unroll
  for (int i = 0; i < 4; i++)
    dst[(size_t)(n0 + yy + 8 * i) * DIM + k0 + xx] =
        __float2half(tile[xx][yy + 8 * i]);
}

// ---------------- fp16 GEMM (measured-best config, untouched) --------------
#define AST 40
#define A_HS (64 * AST)
#define B_HS (256 * AST)
#define NST 3
#define GEMM_SMEM (NST * (A_HS + B_HS) * 2)

template <int QKV>
__global__ __launch_bounds__(256, 2) void gemm_f16(
    const __half* __restrict__ A, const __half* __restrict__ Wt,
    const float* __restrict__ b0, const float* __restrict__ b1,
    const float* __restrict__ b2, float* __restrict__ Cf,
    __half* __restrict__ H0, __half* __restrict__ H1,
    __half* __restrict__ H2, int M) {
  extern __shared__ __half smh[];
  const uint32_t sm_u = smem_u32(smh);

  const int t = threadIdx.x;
  const int m0 = blockIdx.y * 64;
  const int n0g = blockIdx.x * 256;
  const int warp = t >> 5, lane = t & 31;
  const int wm = (warp & 1) * 32;
  const int wn = (warp >> 1) * 64;
  const int g = lane >> 2, t4 = lane & 3;
  const int ar = lane & 15, aklo = (lane & 16) >> 1;
  const int br = (lane & 7) + ((lane & 16) >> 1), bklo = lane & 8;

  float c[2][8][4];
#pragma unroll
  for (int i = 0; i < 2; i++)
#pragma unroll
    for (int j = 0; j < 8; j++)
#pragma unroll
      for (int r = 0; r < 4; r++) c[i][j][r] = 0.f;

  auto prefetch = [&](int buf, int k0) {
    __half* asb = smh + buf * (A_HS + B_HS);
    __half* bsb = asb + A_HS;
    {
      int row = t >> 2, c8 = (t & 3) << 3;
      int gr = m0 + row;
      if (gr >= M) gr = M - 1;
      unsigned dst = (unsigned)__cvta_generic_to_shared(asb + row * AST + c8);
      asm volatile("cp.async.cg.shared.global [%0], [%1], 16;" ::"r"(dst),
                   "l"(A + (size_t)gr * DIM + k0 + c8));
    }
#pragma unroll
    for (int i = 0; i < 4; i++) {
      int idx = t + 256 * i;
      int row = idx >> 2, c8 = (idx & 3) << 3;
      unsigned dst = (unsigned)__cvta_generic_to_shared(bsb + row * AST + c8);
      asm volatile("cp.async.cg.shared.global [%0], [%1], 16;" ::"r"(dst),
                   "l"(Wt + (size_t)(n0g + row) * DIM + k0 + c8));
    }
  };

  prefetch(0, 0);
  asm volatile("cp.async.commit_group;");
  prefetch(1, 32);
  asm volatile("cp.async.commit_group;");

  const int KT = DIM / 32;
  for (int kt = 0; kt < KT; kt++) {
    const int s = kt % 3;
    asm volatile("cp.async.wait_group 1;");
    __syncthreads();

    const uint32_t au = sm_u + s * (A_HS + B_HS) * 2;
    const uint32_t bu = au + A_HS * 2;

#pragma unroll
    for (int kk = 0; kk < 32; kk += 16) {
      unsigned av[2][4], bv[4][4];
#pragma unroll
      for (int am = 0; am < 2; am++)
        ldsm4(av[am], au + ((wm + 16 * am + ar) * AST + kk + aklo) * 2);
#pragma unroll
      for (int bn = 0; bn < 4; bn++)
        ldsm4(bv[bn], bu + ((wn + 16 * bn + br) * AST + kk + bklo) * 2);
#pragma unroll
      for (int am = 0; am < 2; am++)
#pragma unroll
        for (int an = 0; an < 8; an++)
          mma_f16(c[am][an], av[am], (an & 1) ? (bv[an >> 1] + 2) : bv[an >> 1]);
    }

    if (kt + 2 < KT) prefetch((kt + 2) % 3, (kt + 2) * 32);
    asm volatile("cp.async.commit_group;");
  }

  // ---- epilogue ----
  int part = 0, ncol0 = n0g;
  const float* bias = b0;
  if (QKV) {
    part = n0g / DIM;
    ncol0 = n0g - part * DIM;
    bias = (part == 0) ? b0 : (part == 1) ? b1 : b2;
  }
  __half* H = QKV ? ((part == 0) ? H0 : (part == 1) ? H1 : H2) : (__half*)0;
#pragma unroll
  for (int am = 0; am < 2; am++) {
    const int r0 = m0 + wm + 16 * am + g;
    const int r1 = r0 + 8;
#pragma unroll
    for (int an = 0; an < 8; an++) {
      const int col = ncol0 + wn + 8 * an + 2 * t4;
      const float bb0 = bias[col], bb1 = bias[col + 1];
      if (!QKV) {
        if (r0 < M)
          *(float2*)(Cf + (size_t)r0 * DIM + col) =
              make_float2(c[am][an][0] + bb0, c[am][an][1] + bb1);
        if (r1 < M)
          *(float2*)(Cf + (size_t)r1 * DIM + col) =
              make_float2(c[am][an][2] + bb0, c[am][an][3] + bb1);
      } else {
        if (r0 < M)
          *(__half2*)(H + (size_t)r0 * DIM + col) =
              __floats2half2_rn(c[am][an][0] + bb0, c[am][an][1] + bb1);
        if (r1 < M)
          *(__half2*)(H + (size_t)r1 * DIM + col) =
              __floats2half2_rn(c[am][an][2] + bb0, c[am][an][3] + bb1);
      }
    }
  }
}

// ---------------- fused RMSNorm + RoPE; folds SCALE into Q; resets ctr -----
__global__ __launch_bounds__(512) void rms_rope_kernel(
    __half* __restrict__ qbuf, __half* __restrict__ kbuf,
    const float* __restrict__ gq, const float* __restrict__ gk,
    const float* __restrict__ cosp, const float* __restrict__ sinp) {
  if (blockIdx.x == 0 && threadIdx.x == 0) g_ctr = ATT_GRID;
  const int l = blockIdx.x;
  const int half = threadIdx.x >> 8;
  __half* row = (half == 0) ? (qbuf + (size_t)l * DIM) : (kbuf + (size_t)l * DIM);
  const float* g = (half == 0) ? gq : gk;
  const float post = (half == 0) ? SCALE_F : 1.0f;   // fold attention scale into Q
  const int t = threadIdx.x & 255;

  float2 v[3], cs[3], gv[3];
  float ss = 0.f;
#pragma unroll
  for (int j = 0; j < 3; j++) {
    int p = t + 256 * j;
    v[j] = __half22float2(((const __half2*)row)[p]);
    int hd2 = p & 63;
    cs[j] = make_float2(cosp[l * 64 + hd2], sinp[l * 64 + hd2]);
    gv[j] = *(const float2*)(g + 2 * p);
    ss += v[j].x * v[j].x + v[j].y * v[j].y;
  }
#pragma unroll
  for (int off = 16; off > 0; off >>= 1)
    ss += __shfl_xor_sync(0xffffffffu, ss, off);
  __shared__ float red[2][8];
  if ((t & 31) == 0) red[half][t >> 5] = ss;
  __syncthreads();
  float tot = 0.f;
#pragma unroll
  for (int w = 0; w < 8; w++) tot += red[half][w];
  const float r = rsqrtf(tot * (1.0f / (float)DIM) + 1e-6f) * post;

#pragma unroll
  for (int j = 0; j < 3; j++) {
    int p = t + 256 * j;
    float e = v[j].x * r * gv[j].x;
    float o = v[j].y * r * gv[j].y;
    ((__half2*)row)[p] =
        __floats2half2_rn(e * cs[j].x - o * cs[j].y, e * cs[j].y + o * cs[j].x);
  }
}

// ---------------- persistent fp16 flash attention (work-stealing) ----------
#define TILE_H (64 * 136)
#define ATT_SMEM (4 * TILE_H * 2)   // Q + K0 + K1 + V (68 KB)

__global__ __launch_bounds__(128, 3) void attn_f16_kernel(
    const __half* __restrict__ q, const __half* __restrict__ k,
    const __half* __restrict__ v, __half* __restrict__ o) {
  extern __shared__ __half smh[];
  __shared__ int s_next;
  const uint32_t qs_u = smem_u32(smh);
  const uint32_t k0_u = qs_u + TILE_H * 2;
  const uint32_t k1_u = k0_u + TILE_H * 2;
  const uint32_t vb_u = k1_u + TILE_H * 2;

  const int t = threadIdx.x, lane = t & 31, w = t >> 5;
  const int g = lane >> 2, t4 = lane & 3;
  const int rw = w * 16;
  const int ar = lane & 15, aklo = (lane & 16) >> 1;
  const int br = (lane & 7) + ((lane & 16) >> 1), bklo = lane & 8;
  const int vrow = lane & 15, vcol = (lane >> 4) << 3;

  int unit = blockIdx.x;

  while (unit < NUNITS) {
    const int ub = unit / NH;
    const int h = unit - ub * NH;
    const int blk = NQB - 1 - ub;          // LPT: long blocks first
    const int q0 = blk * 64;

    auto load_tile = [&](const __half* src, uint32_t dst_u, int kb) {
#pragma unroll
      for (int i = 0; i < 8; i++) {
        int idx = t + 128 * i, r = idx >> 4, c8 = (idx & 15) << 3;
        int kr = kb + r;
        int sz = (kr < L_TOK) ? 16 : 0;
        if (kr >= L_TOK) kr = L_TOK - 1;
        asm volatile("cp.async.cg.shared.global [%0], [%1], 16, %2;" ::
                     "r"(dst_u + (uint32_t)(r * 136 + c8) * 2),
                     "l"(src + (size_t)kr * DIM + h * HD + c8), "r"(sz));
      }
    };

    load_tile(q, qs_u, q0);
    load_tile(k, k0_u, 0);
    asm volatile("cp.async.commit_group;");

    float oa[16][4];
#pragma unroll
    for (int a = 0; a < 16; a++)
#pragma unroll
      for (int r = 0; r < 4; r++) oa[a][r] = 0.f;

    float m0 = -3.0e38f, m1 = -3.0e38f, l0 = 0.f, l1 = 0.f;
    const int km0 = (q0 + rw + g < FR) ? FR : L_TOK;
    const int km1 = (q0 + rw + 8 + g < FR) ? FR : L_TOK;

    int qlast = q0 + 63; if (qlast >= L_TOK) qlast = L_TOK - 1;
    const int nt = (((qlast < FR) ? FR : L_TOK) + 63) >> 6;

    for (int kt = 0; kt < nt; kt++) {
      const int kb = kt * 64;
      const uint32_t ku = (kt & 1) ? k1_u : k0_u;
      asm volatile("cp.async.wait_group 0;");
      __syncthreads();

      load_tile(v, vb_u, kb);
      asm volatile("cp.async.commit_group;");
      const bool pk = (kt + 1 < nt);
      if (pk) {
        load_tile(k, ((kt + 1) & 1) ? k1_u : k0_u, kb + 64);
        asm volatile("cp.async.commit_group;");
      }

      // ---- S = Q K^T (Q pre-scaled by 1/sqrt(HD)) ----
      float s_[8][4];
#pragma unroll
      for (int a = 0; a < 8; a++)
#pragma unroll
        for (int r = 0; r < 4; r++) s_[a][r] = 0.f;

#pragma unroll
      for (int k16 = 0; k16 < 8; k16++) {
        const int kk = k16 * 16;
        unsigned av[4], bv[4][4];
        ldsm4(av, qs_u + ((rw + ar) * 136 + kk + aklo) * 2);
#pragma unroll
        for (int bn = 0; bn < 4; bn++)
          ldsm4(bv[bn], ku + ((16 * bn + br) * 136 + kk + bklo) * 2);
#pragma unroll
        for (int a = 0; a < 8; a++)
          mma_f16(s_[a], av, (a & 1) ? (bv[a >> 1] + 2) : bv[a >> 1]);
      }

      // ---- mask only (scale already folded into Q) ----
#pragma unroll
      for (int a = 0; a < 8; a++) {
        int cb = kb + 8 * a + 2 * t4;
        if (cb     >= km0) s_[a][0] = -3.0e38f;
        if (cb + 1 >= km0) s_[a][1] = -3.0e38f;
        if (cb     >= km1) s_[a][2] = -3.0e38f;
        if (cb + 1 >= km1) s_[a][3] = -3.0e38f;
      }

      // ---- warp-local softmax ----
      float mx0 = -3.0e38f, mx1 = -3.0e38f;
#pragma unroll
      for (int a = 0; a < 8; a++) {
        mx0 = fmaxf(mx0, fmaxf(s_[a][0], s_[a][1]));
        mx1 = fmaxf(mx1, fmaxf(s_[a][2], s_[a][3]));
      }
      mx0 = fmaxf(mx0, __shfl_xor_sync(0xffffffffu, mx0, 1));
      mx0 = fmaxf(mx0, __shfl_xor_sync(0xffffffffu, mx0, 2));
      mx1 = fmaxf(mx1, __shfl_xor_sync(0xffffffffu, mx1, 1));
      mx1 = fmaxf(mx1, __shfl_xor_sync(0xffffffffu, mx1, 2));
      const float mn0 = fmaxf(m0, mx0), mn1 = fmaxf(m1, mx1);
      const float cr0 = __expf(m0 - mn0), cr1 = __expf(m1 - mn1);
      m0 = mn0; m1 = mn1;

      unsigned pa[4][4];
      float sl0 = 0.f, sl1 = 0.f;
#pragma unroll
      for (int jk = 0; jk < 4; jk++) {
#pragma unroll
        for (int hh = 0; hh < 2; hh++) {
          const int a = 2 * jk + hh;
          float e0 = __expf(s_[a][0] - mn0);
          float e1 = __expf(s_[a][1] - mn0);
          float e2 = __expf(s_[a][2] - mn1);
          float e3 = __expf(s_[a][3] - mn1);
          sl0 += e0 + e1; sl1 += e2 + e3;
          pa[jk][2 * hh] = h2u(e0, e1);
          pa[jk][2 * hh + 1] = h2u(e2, e3);
        }
      }
      sl0 += __shfl_xor_sync(0xffffffffu, sl0, 1);
      sl0 += __shfl_xor_sync(0xffffffffu, sl0, 2);
      sl1 += __shfl_xor_sync(0xffffffffu, sl1, 1);
      sl1 += __shfl_xor_sync(0xffffffffu, sl1, 2);
      l0 = l0 * cr0 + sl0;
      l1 = l1 * cr1 + sl1;

#pragma unroll
      for (int a = 0; a < 16; a++) {
        oa[a][0] *= cr0; oa[a][1] *= cr0;
        oa[a][2] *= cr1; oa[a][3] *= cr1;
      }

      if (pk) asm volatile("cp.async.wait_group 1;");
      else    asm volatile("cp.async.wait_group 0;");
      __syncthreads();

      // ---- O += P V ----
#pragma unroll
      for (int jk = 0; jk < 4; jk++) {
        const int kk = jk * 16;
        unsigned bv[8][4];
#pragma unroll
        for (int nb = 0; nb < 8; nb++)
          ldsm4t(bv[nb], vb_u + ((kk + vrow) * 136 + 16 * nb + vcol) * 2);
#pragma unroll
        for (int na = 0; na < 16; na++)
          mma_f16(oa[na], pa[jk], (na & 1) ? (bv[na >> 1] + 2) : bv[na >> 1]);
      }
    }

    // ---- unit epilogue ----
    const float inv0 = 1.0f / l0, inv1 = 1.0f / l1;
    const int gr0 = q0 + rw + g, gr1 = gr0 + 8;
#pragma unroll
    for (int na = 0; na < 16; na++) {
      const int col = h * HD + 8 * na + 2 * t4;
      if (gr0 < L_TOK)
        *(__half2*)(o + (size_t)gr0 * DIM + col) =
            __floats2half2_rn(oa[na][0] * inv0, oa[na][1] * inv0);
      if (gr1 < L_TOK)
        *(__half2*)(o + (size_t)gr1 * DIM + col) =
            __floats2half2_rn(oa[na][2] * inv1, oa[na][3] * inv1);
    }

    // ---- steal next unit (next s_next write is fenced by the kt-loop
    //      __syncthreads of the next unit, so no trailing barrier needed) ----
    if (t == 0) s_next = atomicAdd(&g_ctr, 1);
    __syncthreads();
    unit = s_next;
  }
}

// ---------------- launch ----------------
extern "C" void kernel_launch(void* const* d_in, const int* in_sizes, int n_in,
                              void* d_out, int out_size) {
  const float* x  = (const float*)d_in[0];
  const float* wq = (const float*)d_in[1];
  const float* wk = (const float*)d_in[2];
  const float* wv = (const float*)d_in[3];
  const float* wo = (const float*)d_in[4];
  const float* bq = (const float*)d_in[5];
  const float* bk = (const float*)d_in[6];
  const float* bv = (const float*)d_in[7];
  const float* bo = (const float*)d_in[8];
  const float* gq = (const float*)d_in[9];
  const float* gk = (const float*)d_in[10];
  const float* fc = (const float*)d_in[11];
  const float* fs = (const float*)d_in[12];
  float* out = (float*)d_out;

  __half *qb, *kb, *vb, *ab, *xh, *wqkv, *wot;
  cudaGetSymbolAddress((void**)&qb, g_q);
  cudaGetSymbolAddress((void**)&kb, g_k);
  cudaGetSymbolAddress((void**)&vb, g_v);
  cudaGetSymbolAddress((void**)&ab, g_a);
  cudaGetSymbolAddress((void**)&xh, g_xh);
  cudaGetSymbolAddress((void**)&wqkv, g_wqkv);
  cudaGetSymbolAddress((void**)&wot, g_wo);

  cudaFuncSetAttribute(gemm_f16<1>, cudaFuncAttributeMaxDynamicSharedMemorySize, GEMM_SMEM);
  cudaFuncSetAttribute(gemm_f16<0>, cudaFuncAttributeMaxDynamicSharedMemorySize, GEMM_SMEM);
  cudaFuncSetAttribute(attn_f16_kernel, cudaFuncAttributeMaxDynamicSharedMemorySize, ATT_SMEM);

  cvt_all_kernel<<<dim3(DIM / 32, DIM / 32, 5), 256>>>(
      x, wq, wk, wv, wo, xh, wqkv, wot);

  gemm_f16<1><<<dim3(3 * DIM / 256, (L_TOK + 63) / 64), 256, GEMM_SMEM>>>(
      xh, wqkv, bq, bk, bv, nullptr, qb, kb, vb, L_TOK);

  rms_rope_kernel<<<L_TOK, 512>>>(qb, kb, gq, gk, fc, fs);

  attn_f16_kernel<<<ATT_GRID, 128, ATT_SMEM>>>(qb, kb, vb, ab);

  gemm_f16<0><<<dim3(DIM / 256, (L_TOK + 63) / 64), 256, GEMM_SMEM>>>(
      ab, wot, bo, nullptr, nullptr, out, nullptr, nullptr, nullptr, L_TOK);
}